// round 4
// baseline (speedup 1.0000x reference)
#include <cuda_runtime.h>
#include <cuda_bf16.h>
#include <cstdint>

// Problem constants
#define NROWS   8192
#define DIN     1024
#define DHID    16384
#define TOPK    32
#define BANDCAP 64

// Output layout (validated in R3: x_hat region compared correctly):
//   x_hat    [8192,1024]   @ 0
//   z_sparse [8192,16384]  @ 8388608
//   z        [8192,16384]  @ 142606336
//   active   scalar        @ 276824064
#define OFF_XHAT   0
#define OFF_ZSP    8388608
#define OFF_Z      142606336
#define OFF_ACT    276824064

// -------- device scratch (no allocations allowed) --------
__device__ float g_WdecT[(size_t)DHID * DIN];   // 64 MB: W_dec transposed [h][d]
__device__ float g_vals[NROWS * TOPK];
__device__ int   g_idxs[NROWS * TOPK];
__device__ int   g_band_idx[NROWS * BANDCAP];
__device__ int   g_band_cnt[NROWS];
__device__ int   g_sure_cnt[NROWS];
__device__ int   g_pos;

// ---------------- reset ----------------
__global__ void reset_kernel() { g_pos = 0; }

// ---------------- zero-fill z_sparse ----------------
__global__ void fill0_kernel(float4* __restrict__ p) {
    int i = blockIdx.x * blockDim.x + threadIdx.x;   // 131072 * 256 = 33,554,432 float4
    p[i] = make_float4(0.f, 0.f, 0.f, 0.f);
}

// ---------------- W_dec transpose: [DIN,DHID] -> [DHID,DIN] ----------------
__global__ void transpose_kernel(const float* __restrict__ Wdec, float* __restrict__ WdecT) {
    __shared__ float tile[32][33];
    int h0 = blockIdx.x * 32;
    int d0 = blockIdx.y * 32;
    int tx = threadIdx.x, ty = threadIdx.y;          // (32, 8)
#pragma unroll
    for (int j = 0; j < 32; j += 8)
        tile[ty + j][tx] = Wdec[(size_t)(d0 + ty + j) * DHID + h0 + tx];
    __syncthreads();
#pragma unroll
    for (int j = 0; j < 32; j += 8)
        WdecT[(size_t)(h0 + ty + j) * DIN + d0 + tx] = tile[tx][ty + j];
}

// ---------------- encoder: z = relu(x @ W_enc^T), fp32 SGEMM ----------------
__global__ __launch_bounds__(256, 2)
void sgemm_relu_kernel(const float* __restrict__ A, const float* __restrict__ B,
                       float* __restrict__ C) {
    __shared__ float As[16][132];
    __shared__ float Bs[16][132];

    const int tid = threadIdx.x;
    const int tx = tid & 15, ty = tid >> 4;
    const int m0 = blockIdx.y * 128, n0 = blockIdx.x * 128;
    const int lr = tid >> 2;            // 0..63
    const int lc = (tid & 3) * 4;       // 0,4,8,12

    const float* Ag = A + (size_t)(m0 + lr) * DIN + lc;
    const float* Bg = B + (size_t)(n0 + lr) * DIN + lc;

    float acc[8][8];
#pragma unroll
    for (int i = 0; i < 8; i++)
#pragma unroll
        for (int j = 0; j < 8; j++) acc[i][j] = 0.f;

    float4 a0 = *(const float4*)(Ag);
    float4 a1 = *(const float4*)(Ag + (size_t)64 * DIN);
    float4 b0 = *(const float4*)(Bg);
    float4 b1 = *(const float4*)(Bg + (size_t)64 * DIN);

    for (int k0 = 0; k0 < DIN; k0 += 16) {
        As[lc + 0][lr] = a0.x; As[lc + 1][lr] = a0.y; As[lc + 2][lr] = a0.z; As[lc + 3][lr] = a0.w;
        As[lc + 0][lr + 64] = a1.x; As[lc + 1][lr + 64] = a1.y; As[lc + 2][lr + 64] = a1.z; As[lc + 3][lr + 64] = a1.w;
        Bs[lc + 0][lr] = b0.x; Bs[lc + 1][lr] = b0.y; Bs[lc + 2][lr] = b0.z; Bs[lc + 3][lr] = b0.w;
        Bs[lc + 0][lr + 64] = b1.x; Bs[lc + 1][lr + 64] = b1.y; Bs[lc + 2][lr + 64] = b1.z; Bs[lc + 3][lr + 64] = b1.w;
        __syncthreads();

        if (k0 + 16 < DIN) {
            a0 = *(const float4*)(Ag + k0 + 16);
            a1 = *(const float4*)(Ag + (size_t)64 * DIN + k0 + 16);
            b0 = *(const float4*)(Bg + k0 + 16);
            b1 = *(const float4*)(Bg + (size_t)64 * DIN + k0 + 16);
        }

#pragma unroll
        for (int kk = 0; kk < 16; kk++) {
            float ar[8], br[8];
            *(float4*)(ar)     = *(const float4*)&As[kk][ty * 8];
            *(float4*)(ar + 4) = *(const float4*)&As[kk][ty * 8 + 4];
            *(float4*)(br)     = *(const float4*)&Bs[kk][tx * 8];
            *(float4*)(br + 4) = *(const float4*)&Bs[kk][tx * 8 + 4];
#pragma unroll
            for (int i = 0; i < 8; i++)
#pragma unroll
                for (int j = 0; j < 8; j++)
                    acc[i][j] += ar[i] * br[j];
        }
        __syncthreads();
    }

#pragma unroll
    for (int i = 0; i < 8; i++) {
        size_t off = (size_t)(m0 + ty * 8 + i) * DHID + n0 + tx * 8;
        float4 r0, r1;
        r0.x = fmaxf(acc[i][0], 0.f); r0.y = fmaxf(acc[i][1], 0.f);
        r0.z = fmaxf(acc[i][2], 0.f); r0.w = fmaxf(acc[i][3], 0.f);
        r1.x = fmaxf(acc[i][4], 0.f); r1.y = fmaxf(acc[i][5], 0.f);
        r1.z = fmaxf(acc[i][6], 0.f); r1.w = fmaxf(acc[i][7], 0.f);
        *(float4*)(C + off)     = r0;
        *(float4*)(C + off + 4) = r1;
    }
}

// ---------------- top-k stage 1: radix-select 32nd value + band partition ----
// One block (256 threads) per row. Exact radix-select on non-negative float
// bits gives T = our 32nd-largest. Values > T+M are surely in the true top-k
// (M = 300 sigma of our GEMM rounding error); values in [T-M, T+M] form an
// ambiguous band resolved in fp64 by refine_kernel.
__global__ void topk_kernel(const float* __restrict__ z, float* __restrict__ z_sp) {
    extern __shared__ unsigned sb[];            // 16384 x u32
    __shared__ int hist[2048];
    __shared__ unsigned s_prefix;
    __shared__ int s_need;
    __shared__ int sureCnt, bandCnt;

    const int row = blockIdx.x, t = threadIdx.x;
    const float* zr = z + (size_t)row * DHID;

    for (int i = t; i < DHID; i += 256) sb[i] = __float_as_uint(zr[i]);
    if (t == 0) { sureCnt = 0; bandCnt = 0; }
    __syncthreads();

    unsigned prefix = 0;
    int curShift = 32;
    int need = TOPK;
    const int SH[4] = {21, 13, 5, 0};

#pragma unroll
    for (int l = 0; l < 4; l++) {
        const int shift = SH[l];
        const int nb = 1 << (curShift - shift);
        for (int i = t; i < nb; i += 256) hist[i] = 0;
        __syncthreads();
        for (int i = t; i < DHID; i += 256) {
            unsigned b = sb[i];
            if (curShift >= 32 || (b >> curShift) == prefix)
                atomicAdd(&hist[(b >> shift) & (nb - 1)], 1);
        }
        __syncthreads();
        if (t == 0) {
            int nd = need, bb;
            for (bb = nb - 1; bb > 0; bb--) {
                int c = hist[bb];
                if (c >= nd) break;
                nd -= c;
            }
            s_prefix = (prefix << (curShift - shift)) | (unsigned)bb;
            s_need = nd;
        }
        __syncthreads();
        prefix = s_prefix;
        need = s_need;
        curShift = shift;
        __syncthreads();
    }

    const float Tf = __uint_as_float(prefix);   // our exact 32nd-largest value
    const float M  = 1e-4f;
    const float hi = Tf + M, lo = Tf - M;

    for (int i = t; i < DHID; i += 256) {
        float v = __uint_as_float(sb[i]);
        if (v > hi) {
            int s = atomicAdd(&sureCnt, 1);
            g_vals[row * TOPK + s] = v;
            g_idxs[row * TOPK + s] = i;
            z_sp[(size_t)row * DHID + i] = v;
        } else if (v >= lo) {
            int e = atomicAdd(&bandCnt, 1);
            if (e < BANDCAP) g_band_idx[row * BANDCAP + e] = i;
        }
    }
    __syncthreads();
    if (t == 0) {
        g_sure_cnt[row] = sureCnt;
        g_band_cnt[row] = min(bandCnt, BANDCAP);
    }
}

// ---------------- top-k stage 2: fp64 band refinement ----------------------
// One block (128 threads) per row. If the band is contested (more candidates
// than open slots), recompute candidate dot products in fp64 (exact true
// ranking) and select; ties (fp64-equal) break to lowest index. Finally sort
// the 32 selections by index for a fully deterministic pipeline.
__global__ void refine_kernel(const float* __restrict__ z,
                              const float* __restrict__ x,
                              const float* __restrict__ Wenc,
                              float* __restrict__ z_sp) {
    __shared__ double sc[BANDCAP];
    __shared__ int   bidx[BANDCAP];
    __shared__ float bval[BANDCAP];

    const int row = blockIdx.x, t = threadIdx.x;   // 128 threads
    const int sure = g_sure_cnt[row];
    const int bc   = g_band_cnt[row];
    const int need = TOPK - sure;

    if (t < bc) {
        int ix = g_band_idx[row * BANDCAP + t];
        bidx[t] = ix;
        bval[t] = z[(size_t)row * DHID + ix];
    }
    __syncthreads();

    if (bc > need) {   // contested: exact fp64 scores (rare: ~tens of rows total)
        const int wid = t >> 5, lane = t & 31;
        const float* xr = x + (size_t)row * DIN;
        for (int c = wid; c < bc; c += 4) {
            const float* wr = Wenc + (size_t)bidx[c] * DIN;
            double s = 0.0;
            for (int j = lane; j < DIN; j += 32)
                s += (double)xr[j] * (double)wr[j];
#pragma unroll
            for (int o = 16; o; o >>= 1)
                s += __shfl_down_sync(0xffffffffu, s, o);
            if (lane == 0) sc[c] = s;
        }
    }
    __syncthreads();

    if (t == 0) {
        int nsel = 0;
        int sel[BANDCAP];
        if (bc <= need) {
            for (int c = 0; c < bc; c++) sel[nsel++] = c;
        } else {
            bool taken[BANDCAP];
            for (int c = 0; c < bc; c++) taken[c] = false;
            for (int r = 0; r < need; r++) {
                int best = -1;
                for (int c = 0; c < bc; c++) {
                    if (taken[c]) continue;
                    if (best < 0 || sc[c] > sc[best] ||
                        (sc[c] == sc[best] && bidx[c] < bidx[best])) best = c;
                }
                taken[best] = true;
                sel[nsel++] = best;
            }
        }
        for (int a = 0; a < nsel; a++) {
            int c = sel[a];
            g_vals[row * TOPK + sure + a] = bval[c];
            g_idxs[row * TOPK + sure + a] = bidx[c];
            z_sp[(size_t)row * DHID + bidx[c]] = bval[c];
        }
        for (int a = sure + nsel; a < TOPK; a++) {   // unreachable in practice
            g_vals[row * TOPK + a] = 0.f;
            g_idxs[row * TOPK + a] = 0;
        }
        // deterministic order: sort the 32 by index
        for (int a = 1; a < TOPK; a++) {
            float v = g_vals[row * TOPK + a];
            int   ix = g_idxs[row * TOPK + a];
            int b = a - 1;
            while (b >= 0 && g_idxs[row * TOPK + b] > ix) {
                g_vals[row * TOPK + b + 1] = g_vals[row * TOPK + b];
                g_idxs[row * TOPK + b + 1] = g_idxs[row * TOPK + b];
                b--;
            }
            g_vals[row * TOPK + b + 1] = v;
            g_idxs[row * TOPK + b + 1] = ix;
        }
        int pos = 0;
        for (int a = 0; a < TOPK; a++)
            if (g_vals[row * TOPK + a] > 0.f) pos++;
        atomicAdd(&g_pos, pos);
    }
}

// ---------------- decoder: x_hat[n,:] = sum_k vals * W_decT[idx,:] ----------
__global__ void decoder_kernel(const float* __restrict__ WdecT, float* __restrict__ xhat) {
    __shared__ float sv[TOPK];
    __shared__ int   si[TOPK];
    const int row = blockIdx.x, t = threadIdx.x;   // 256 threads, 4 outputs each
    if (t < TOPK) { sv[t] = g_vals[row * TOPK + t]; si[t] = g_idxs[row * TOPK + t]; }
    __syncthreads();
    const int d = t * 4;
    float x0 = 0.f, x1 = 0.f, x2 = 0.f, x3 = 0.f;
#pragma unroll
    for (int k = 0; k < TOPK; k++) {
        float v = sv[k];
        const float4 w = *(const float4*)(WdecT + (size_t)si[k] * DIN + d);
        x0 += v * w.x; x1 += v * w.y; x2 += v * w.z; x3 += v * w.w;
    }
    *(float4*)(xhat + (size_t)row * DIN + d) = make_float4(x0, x1, x2, x3);
}

// ---------------- active = mean nonzero count ----------------
__global__ void finalize_kernel(float* __restrict__ act) {
    *act = (float)g_pos / (float)NROWS;
}

// ---------------- launch ----------------
extern "C" void kernel_launch(void* const* d_in, const int* in_sizes, int n_in,
                              void* d_out, int out_size) {
    const float* x     = (const float*)d_in[0];
    const float* W_enc = (const float*)d_in[1];
    const float* W_dec = (const float*)d_in[2];
    float* out = (float*)d_out;

    float* xhat = out + OFF_XHAT;
    float* z_sp = out + OFF_ZSP;
    float* z    = out + OFF_Z;
    float* act  = out + OFF_ACT;

    float* WdecT;
    cudaGetSymbolAddress((void**)&WdecT, g_WdecT);

    cudaFuncSetAttribute(topk_kernel, cudaFuncAttributeMaxDynamicSharedMemorySize, 65536);

    reset_kernel<<<1, 1>>>();
    fill0_kernel<<<131072, 256>>>((float4*)z_sp);
    transpose_kernel<<<dim3(DHID / 32, DIN / 32), dim3(32, 8)>>>(W_dec, WdecT);
    sgemm_relu_kernel<<<dim3(DHID / 128, NROWS / 128), 256>>>(x, W_enc, z);
    topk_kernel<<<NROWS, 256, 65536>>>(z, z_sp);
    refine_kernel<<<NROWS, 128>>>(z, x, W_enc, z_sp);
    decoder_kernel<<<NROWS, 256>>>(WdecT, xhat);
    finalize_kernel<<<1, 1>>>(act);
}

// round 6
// speedup vs baseline: 1.8440x; 1.8440x over previous
#include <cuda_runtime.h>
#include <cuda_bf16.h>
#include <cstdint>

// Problem constants
#define NROWS   8192
#define DIN     1024
#define DHID    16384
#define TOPK    32
#define BANDCAP 64

// Output layout:
//   x_hat    [8192,1024]   @ 0
//   z_sparse [8192,16384]  @ 8388608
//   z        [8192,16384]  @ 142606336
//   active   scalar        @ 276824064
#define OFF_XHAT   0
#define OFF_ZSP    8388608
#define OFF_Z      142606336
#define OFF_ACT    276824064

// -------- device scratch (no allocations allowed) --------
__device__ float g_WdecT[(size_t)DHID * DIN];                                // 64 MB
__device__ __align__(256) unsigned char g_xhi[(size_t)NROWS * DIN * 2];      // 16 MB
__device__ __align__(256) unsigned char g_xlo[(size_t)NROWS * DIN * 2];
__device__ __align__(256) unsigned char g_whi[(size_t)DHID * DIN * 2];       // 32 MB
__device__ __align__(256) unsigned char g_wlo[(size_t)DHID * DIN * 2];
__device__ float g_vals[NROWS * TOPK];
__device__ int   g_idxs[NROWS * TOPK];
__device__ int   g_band_idx[NROWS * BANDCAP];
__device__ int   g_band_cnt[NROWS];
__device__ int   g_sure_cnt[NROWS];
__device__ int   g_pos;

// ---------------- PTX helpers (baseline compute_103 feature set only) -------
__device__ __forceinline__ uint32_t smem_u32(const void* p) {
    uint32_t a;
    asm("{ .reg .u64 t; cvta.to.shared.u64 t, %1; cvt.u32.u64 %0, t; }" : "=r"(a) : "l"(p));
    return a;
}
__device__ __forceinline__ void cp16(uint32_t dst, const void* src) {
    asm volatile("cp.async.cg.shared.global [%0], [%1], 16;" :: "r"(dst), "l"(src));
}
#define CP_COMMIT() asm volatile("cp.async.commit_group;" ::: "memory")
#define CP_WAIT2()  asm volatile("cp.async.wait_group 2;" ::: "memory")

__device__ __forceinline__ void ldm4(uint32_t* d, uint32_t addr) {
    asm volatile("ldmatrix.sync.aligned.m8n8.x4.shared.b16 {%0,%1,%2,%3}, [%4];"
        : "=r"(d[0]), "=r"(d[1]), "=r"(d[2]), "=r"(d[3]) : "r"(addr));
}
__device__ __forceinline__ void mma_bf16(float* c, const uint32_t* a, const uint32_t* b) {
    asm volatile("mma.sync.aligned.m16n8k16.row.col.f32.bf16.bf16.f32 "
        "{%0,%1,%2,%3}, {%4,%5,%6,%7}, {%8,%9}, {%0,%1,%2,%3};"
        : "+f"(c[0]), "+f"(c[1]), "+f"(c[2]), "+f"(c[3])
        : "r"(a[0]), "r"(a[1]), "r"(a[2]), "r"(a[3]), "r"(b[0]), "r"(b[1]));
}

// ---------------- reset ----------------
__global__ void reset_kernel() { g_pos = 0; }

// ---------------- zero-fill z_sparse ----------------
__global__ void fill0_kernel(float4* __restrict__ p) {
    int i = blockIdx.x * blockDim.x + threadIdx.x;
    p[i] = make_float4(0.f, 0.f, 0.f, 0.f);
}

// ---------------- pack: fp32 -> bf16 hi/lo, plain row-major -----------------
__global__ void pack_kernel(const float* __restrict__ src,
                            unsigned* __restrict__ dhi,
                            unsigned* __restrict__ dlo, int rows) {
    int i = blockIdx.x * blockDim.x + threadIdx.x;     // one thread per 2 elems
    if (i >= rows * (DIN / 2)) return;
    float2 v = ((const float2*)src)[i];
    __nv_bfloat16 h0 = __float2bfloat16_rn(v.x);
    __nv_bfloat16 h1 = __float2bfloat16_rn(v.y);
    __nv_bfloat16 l0 = __float2bfloat16_rn(v.x - __bfloat162float(h0));
    __nv_bfloat16 l1 = __float2bfloat16_rn(v.y - __bfloat162float(h1));
    dhi[i] = ((unsigned)__bfloat16_as_ushort(h1) << 16) | __bfloat16_as_ushort(h0);
    dlo[i] = ((unsigned)__bfloat16_as_ushort(l1) << 16) | __bfloat16_as_ushort(l0);
}

// ---------------- W_dec transpose ----------------
__global__ void transpose_kernel(const float* __restrict__ Wdec, float* __restrict__ WdecT) {
    __shared__ float tile[32][33];
    int h0 = blockIdx.x * 32;
    int d0 = blockIdx.y * 32;
    int tx = threadIdx.x, ty = threadIdx.y;
#pragma unroll
    for (int j = 0; j < 32; j += 8)
        tile[ty + j][tx] = Wdec[(size_t)(d0 + ty + j) * DHID + h0 + tx];
    __syncthreads();
#pragma unroll
    for (int j = 0; j < 32; j += 8)
        WdecT[(size_t)(h0 + ty + j) * DIN + d0 + tx] = tile[tx][ty + j];
}

// ---------------- encoder: legacy-HMMA bf16 3-term split GEMM + relu --------
// CTA 128x128, 8 warps (4x2) with 32x64 warp tiles, K-tile 32, 3-stage
// cp.async pipeline. Smem subtile [128][32]bf16, row 64B = 4 x 16B chunks,
// chunk-XOR swizzle ((c16 ^ (r&3))) for ldmatrix.
#define KTILE   32
#define STAGES  3
#define TILE_B  8192
#define STAGE_B 32768
#define GEMM_SMEM (STAGES * STAGE_B)

__global__ __launch_bounds__(256, 2)
void mma_gemm_kernel(const unsigned char* __restrict__ Ah, const unsigned char* __restrict__ Al,
                     const unsigned char* __restrict__ Bh, const unsigned char* __restrict__ Bl,
                     float* __restrict__ z) {
    extern __shared__ unsigned char smem[];
    const uint32_t sb = smem_u32(smem);
    const int tid = threadIdx.x;
    const int lane = tid & 31, warp = tid >> 5;
    const int wm = warp & 3, wn = warp >> 2;         // 4 x 2 warp grid
    const int m0 = blockIdx.y * 128, n0 = blockIdx.x * 128;

    float acc[2][8][4];
#pragma unroll
    for (int i = 0; i < 2; i++)
#pragma unroll
        for (int j = 0; j < 8; j++)
#pragma unroll
            for (int q = 0; q < 4; q++) acc[i][j][q] = 0.f;

    const unsigned char* gs[4] = {Ah, Al, Bh, Bl};

    // stage loader: 4 subtiles x 512 16B-chunks, 8 cp.async per thread
    auto load_stage = [&](int s, int kc) {
        const uint32_t stage = sb + s * STAGE_B;
#pragma unroll
        for (int t = 0; t < 4; t++) {
            const int r0 = (t < 2) ? m0 : n0;
            const unsigned char* g = gs[t];
#pragma unroll
            for (int rep = 0; rep < 2; rep++) {
                const int j = tid + rep * 256;
                const int r = j >> 2, c16 = j & 3;
                const unsigned char* src = g + (((size_t)(r0 + r) << 10) + kc * 32 + c16 * 8) * 2;
                const uint32_t dst = stage + t * TILE_B + r * 64 + ((c16 ^ (r & 3)) << 4);
                cp16(dst, src);
            }
        }
    };

    load_stage(0, 0); CP_COMMIT();
    load_stage(1, 1); CP_COMMIT();

    for (int kc = 0; kc < DIN / KTILE; kc++) {
        if (kc + 2 < DIN / KTILE) load_stage((kc + 2) % STAGES, kc + 2);
        CP_COMMIT();
        CP_WAIT2();
        __syncthreads();
        const uint32_t stage = sb + (kc % STAGES) * STAGE_B;

#pragma unroll
        for (int ks = 0; ks < 2; ks++) {
            uint32_t ah[2][4], al[2][4], bh[8][2], bl[8][2];
#pragma unroll
            for (int i = 0; i < 2; i++) {
                const int row = wm * 32 + i * 16 + (lane & 15);
                const int c16 = ks * 2 + (lane >> 4);
                const uint32_t off = row * 64 + ((c16 ^ (row & 3)) << 4);
                ldm4(ah[i], stage + off);
                ldm4(al[i], stage + TILE_B + off);
            }
#pragma unroll
            for (int g = 0; g < 4; g++) {
                const int row = wn * 64 + g * 16 + (lane & 7) + ((lane >> 4) << 3);
                const int c16 = ks * 2 + ((lane >> 3) & 1);
                const uint32_t off = row * 64 + ((c16 ^ (row & 3)) << 4);
                uint32_t d[4];
                ldm4(d, stage + 2 * TILE_B + off);
                bh[2 * g][0] = d[0]; bh[2 * g][1] = d[1];
                bh[2 * g + 1][0] = d[2]; bh[2 * g + 1][1] = d[3];
                ldm4(d, stage + 3 * TILE_B + off);
                bl[2 * g][0] = d[0]; bl[2 * g][1] = d[1];
                bl[2 * g + 1][0] = d[2]; bl[2 * g + 1][1] = d[3];
            }
#pragma unroll
            for (int i = 0; i < 2; i++)
#pragma unroll
                for (int j = 0; j < 8; j++) {
                    mma_bf16(acc[i][j], ah[i], bh[j]);
                    mma_bf16(acc[i][j], ah[i], bl[j]);
                    mma_bf16(acc[i][j], al[i], bh[j]);
                }
        }
        __syncthreads();
    }

    // epilogue: relu + store
    const int mbase = m0 + wm * 32, nbase = n0 + wn * 64;
#pragma unroll
    for (int i = 0; i < 2; i++)
#pragma unroll
        for (int j = 0; j < 8; j++) {
            const int r = mbase + i * 16 + (lane >> 2);
            const int c = nbase + j * 8 + (lane & 3) * 2;
            float2 v0, v1;
            v0.x = fmaxf(acc[i][j][0], 0.f); v0.y = fmaxf(acc[i][j][1], 0.f);
            v1.x = fmaxf(acc[i][j][2], 0.f); v1.y = fmaxf(acc[i][j][3], 0.f);
            *(float2*)(z + (size_t)r * DHID + c) = v0;
            *(float2*)(z + (size_t)(r + 8) * DHID + c) = v1;
        }
}

// ---------------- top-k stage 1: radix-select + band partition ---------------
__global__ void topk_kernel(const float* __restrict__ z, float* __restrict__ z_sp) {
    extern __shared__ unsigned sbuf[];
    __shared__ int hist[2048];
    __shared__ unsigned s_prefix;
    __shared__ int s_need;
    __shared__ int sureCnt, bandCnt;

    const int row = blockIdx.x, t = threadIdx.x;
    const float* zr = z + (size_t)row * DHID;

    for (int i = t; i < DHID; i += 256) sbuf[i] = __float_as_uint(zr[i]);
    if (t == 0) { sureCnt = 0; bandCnt = 0; }
    __syncthreads();

    unsigned prefix = 0;
    int curShift = 32;
    int need = TOPK;
    const int SH[4] = {21, 13, 5, 0};

#pragma unroll
    for (int l = 0; l < 4; l++) {
        const int shift = SH[l];
        const int nb = 1 << (curShift - shift);
        for (int i = t; i < nb; i += 256) hist[i] = 0;
        __syncthreads();
        for (int i = t; i < DHID; i += 256) {
            unsigned b = sbuf[i];
            if (curShift >= 32 || (b >> curShift) == prefix)
                atomicAdd(&hist[(b >> shift) & (nb - 1)], 1);
        }
        __syncthreads();
        if (t == 0) {
            int nd = need, bb;
            for (bb = nb - 1; bb > 0; bb--) {
                int c = hist[bb];
                if (c >= nd) break;
                nd -= c;
            }
            s_prefix = (prefix << (curShift - shift)) | (unsigned)bb;
            s_need = nd;
        }
        __syncthreads();
        prefix = s_prefix;
        need = s_need;
        curShift = shift;
        __syncthreads();
    }

    const float Tf = __uint_as_float(prefix);
    const float M  = 1e-4f;
    const float hi = Tf + M, lo = Tf - M;

    for (int i = t; i < DHID; i += 256) {
        float v = __uint_as_float(sbuf[i]);
        if (v > hi) {
            int s = atomicAdd(&sureCnt, 1);
            g_vals[row * TOPK + s] = v;
            g_idxs[row * TOPK + s] = i;
            z_sp[(size_t)row * DHID + i] = v;
        } else if (v >= lo) {
            int e = atomicAdd(&bandCnt, 1);
            if (e < BANDCAP) g_band_idx[row * BANDCAP + e] = i;
        }
    }
    __syncthreads();
    if (t == 0) {
        g_sure_cnt[row] = sureCnt;
        g_band_cnt[row] = min(bandCnt, BANDCAP);
    }
}

// ---------------- top-k stage 2: fp64 band refinement ------------------------
__global__ void refine_kernel(const float* __restrict__ z,
                              const float* __restrict__ x,
                              const float* __restrict__ Wenc,
                              float* __restrict__ z_sp) {
    __shared__ double sc[BANDCAP];
    __shared__ int   bidx[BANDCAP];
    __shared__ float bval[BANDCAP];

    const int row = blockIdx.x, t = threadIdx.x;
    const int sure = g_sure_cnt[row];
    const int bc   = g_band_cnt[row];
    const int need = TOPK - sure;

    if (t < bc) {
        int ix = g_band_idx[row * BANDCAP + t];
        bidx[t] = ix;
        bval[t] = z[(size_t)row * DHID + ix];
    }
    __syncthreads();

    if (bc > need) {   // contested: exact fp64 ranking (rare)
        const int wd = t >> 5, lane = t & 31;
        const float* xr = x + (size_t)row * DIN;
        for (int c = wd; c < bc; c += 4) {
            const float* wr = Wenc + (size_t)bidx[c] * DIN;
            double s = 0.0;
            for (int j = lane; j < DIN; j += 32)
                s += (double)xr[j] * (double)wr[j];
#pragma unroll
            for (int o = 16; o; o >>= 1)
                s += __shfl_down_sync(0xffffffffu, s, o);
            if (lane == 0) sc[c] = s;
        }
    }
    __syncthreads();

    if (t == 0) {
        int nsel = 0;
        int sel[BANDCAP];
        if (bc <= need) {
            for (int c = 0; c < bc; c++) sel[nsel++] = c;
        } else {
            bool taken[BANDCAP];
            for (int c = 0; c < bc; c++) taken[c] = false;
            for (int r = 0; r < need; r++) {
                int best = -1;
                for (int c = 0; c < bc; c++) {
                    if (taken[c]) continue;
                    if (best < 0 || sc[c] > sc[best] ||
                        (sc[c] == sc[best] && bidx[c] < bidx[best])) best = c;
                }
                taken[best] = true;
                sel[nsel++] = best;
            }
        }
        for (int a = 0; a < nsel; a++) {
            int c = sel[a];
            g_vals[row * TOPK + sure + a] = bval[c];
            g_idxs[row * TOPK + sure + a] = bidx[c];
            z_sp[(size_t)row * DHID + bidx[c]] = bval[c];
        }
        for (int a = sure + nsel; a < TOPK; a++) {
            g_vals[row * TOPK + a] = 0.f;
            g_idxs[row * TOPK + a] = 0;
        }
        for (int a = 1; a < TOPK; a++) {
            float v = g_vals[row * TOPK + a];
            int   ix = g_idxs[row * TOPK + a];
            int b = a - 1;
            while (b >= 0 && g_idxs[row * TOPK + b] > ix) {
                g_vals[row * TOPK + b + 1] = g_vals[row * TOPK + b];
                g_idxs[row * TOPK + b + 1] = g_idxs[row * TOPK + b];
                b--;
            }
            g_vals[row * TOPK + b + 1] = v;
            g_idxs[row * TOPK + b + 1] = ix;
        }
        int pos = 0;
        for (int a = 0; a < TOPK; a++)
            if (g_vals[row * TOPK + a] > 0.f) pos++;
        atomicAdd(&g_pos, pos);
    }
}

// ---------------- decoder ----------------
__global__ void decoder_kernel(const float* __restrict__ WdecT, float* __restrict__ xhat) {
    __shared__ float sv[TOPK];
    __shared__ int   si[TOPK];
    const int row = blockIdx.x, t = threadIdx.x;
    if (t < TOPK) { sv[t] = g_vals[row * TOPK + t]; si[t] = g_idxs[row * TOPK + t]; }
    __syncthreads();
    const int d = t * 4;
    float x0 = 0.f, x1 = 0.f, x2 = 0.f, x3 = 0.f;
#pragma unroll
    for (int k = 0; k < TOPK; k++) {
        float v = sv[k];
        const float4 w = *(const float4*)(WdecT + (size_t)si[k] * DIN + d);
        x0 += v * w.x; x1 += v * w.y; x2 += v * w.z; x3 += v * w.w;
    }
    *(float4*)(xhat + (size_t)row * DIN + d) = make_float4(x0, x1, x2, x3);
}

// ---------------- active ----------------
__global__ void finalize_kernel(float* __restrict__ act) {
    *act = (float)g_pos / (float)NROWS;
}

// ---------------- launch ----------------
extern "C" void kernel_launch(void* const* d_in, const int* in_sizes, int n_in,
                              void* d_out, int out_size) {
    const float* x     = (const float*)d_in[0];
    const float* W_enc = (const float*)d_in[1];
    const float* W_dec = (const float*)d_in[2];
    float* out = (float*)d_out;

    float* xhat = out + OFF_XHAT;
    float* z_sp = out + OFF_ZSP;
    float* z    = out + OFF_Z;
    float* act  = out + OFF_ACT;

    float* WdecT;
    cudaGetSymbolAddress((void**)&WdecT, g_WdecT);
    unsigned char *xhi, *xlo, *whi, *wlo;
    cudaGetSymbolAddress((void**)&xhi, g_xhi);
    cudaGetSymbolAddress((void**)&xlo, g_xlo);
    cudaGetSymbolAddress((void**)&whi, g_whi);
    cudaGetSymbolAddress((void**)&wlo, g_wlo);

    cudaFuncSetAttribute(topk_kernel, cudaFuncAttributeMaxDynamicSharedMemorySize, 65536);
    cudaFuncSetAttribute(mma_gemm_kernel, cudaFuncAttributeMaxDynamicSharedMemorySize, GEMM_SMEM);

    reset_kernel<<<1, 1>>>();
    fill0_kernel<<<131072, 256>>>((float4*)z_sp);
    pack_kernel<<<(NROWS * DIN / 2 + 255) / 256, 256>>>(x, (unsigned*)xhi, (unsigned*)xlo, NROWS);
    pack_kernel<<<(DHID * DIN / 2 + 255) / 256, 256>>>(W_enc, (unsigned*)whi, (unsigned*)wlo, DHID);
    transpose_kernel<<<dim3(DHID / 32, DIN / 32), dim3(32, 8)>>>(W_dec, WdecT);
    mma_gemm_kernel<<<dim3(DHID / 128, NROWS / 128), 256, GEMM_SMEM>>>(xhi, xlo, whi, wlo, z);
    topk_kernel<<<NROWS, 256, 65536>>>(z, z_sp);
    refine_kernel<<<NROWS, 128>>>(z, x, W_enc, z_sp);
    decoder_kernel<<<NROWS, 256>>>(WdecT, xhat);
    finalize_kernel<<<1, 1>>>(act);
}

// round 7
// speedup vs baseline: 2.8937x; 1.5692x over previous
#include <cuda_runtime.h>
#include <cuda_bf16.h>
#include <cuda_fp16.h>
#include <cstdint>

// Problem constants
#define NROWS   8192
#define DIN     1024
#define DHID    16384
#define TOPK    32
#define BANDCAP 64

// Output layout:
//   x_hat    [8192,1024]   @ 0
//   z_sparse [8192,16384]  @ 8388608
//   z        [8192,16384]  @ 142606336
//   active   scalar        @ 276824064
#define OFF_XHAT   0
#define OFF_ZSP    8388608
#define OFF_Z      142606336
#define OFF_ACT    276824064

// -------- device scratch (no allocations allowed) --------
__device__ float g_WdecT[(size_t)DHID * DIN];                                // 64 MB
__device__ __align__(256) unsigned char g_xh[(size_t)NROWS * DIN * 2];       // fp16 x
__device__ __align__(256) unsigned char g_wh[(size_t)DHID * DIN * 2];        // fp16 W_enc
__device__ float g_vals[NROWS * TOPK];
__device__ int   g_idxs[NROWS * TOPK];
__device__ int   g_band_idx[NROWS * BANDCAP];
__device__ int   g_band_cnt[NROWS];
__device__ int   g_sure_cnt[NROWS];
__device__ int   g_pos;

// ---------------- PTX helpers (baseline compute_103 feature set only) -------
__device__ __forceinline__ uint32_t smem_u32(const void* p) {
    uint32_t a;
    asm("{ .reg .u64 t; cvta.to.shared.u64 t, %1; cvt.u32.u64 %0, t; }" : "=r"(a) : "l"(p));
    return a;
}
__device__ __forceinline__ void cp16(uint32_t dst, const void* src) {
    asm volatile("cp.async.cg.shared.global [%0], [%1], 16;" :: "r"(dst), "l"(src));
}
#define CP_COMMIT() asm volatile("cp.async.commit_group;" ::: "memory")
#define CP_WAIT2()  asm volatile("cp.async.wait_group 2;" ::: "memory")

__device__ __forceinline__ void ldm4(uint32_t* d, uint32_t addr) {
    asm volatile("ldmatrix.sync.aligned.m8n8.x4.shared.b16 {%0,%1,%2,%3}, [%4];"
        : "=r"(d[0]), "=r"(d[1]), "=r"(d[2]), "=r"(d[3]) : "r"(addr));
}
__device__ __forceinline__ void mma_f16(float* c, const uint32_t* a, const uint32_t* b) {
    asm volatile("mma.sync.aligned.m16n8k16.row.col.f32.f16.f16.f32 "
        "{%0,%1,%2,%3}, {%4,%5,%6,%7}, {%8,%9}, {%0,%1,%2,%3};"
        : "+f"(c[0]), "+f"(c[1]), "+f"(c[2]), "+f"(c[3])
        : "r"(a[0]), "r"(a[1]), "r"(a[2]), "r"(a[3]), "r"(b[0]), "r"(b[1]));
}

// conflict-free chunk swizzle for 64B rows: rows 0..7 hit 8 distinct 16B groups
__device__ __forceinline__ uint32_t swz(int r, int c16) {
    return (uint32_t)(r * 64 + ((c16 ^ ((r >> 1) & 3)) << 4));
}

// ---------------- reset ----------------
__global__ void reset_kernel() { g_pos = 0; }

// ---------------- pack: fp32 -> fp16, row-major -----------------------------
__global__ void packh_kernel(const float* __restrict__ src, unsigned* __restrict__ dst, int n2) {
    int i = blockIdx.x * blockDim.x + threadIdx.x;
    if (i >= n2) return;
    float2 v = ((const float2*)src)[i];
    __half2 h = __floats2half2_rn(v.x, v.y);
    dst[i] = *reinterpret_cast<unsigned*>(&h);
}

// ---------------- W_dec transpose ----------------
__global__ void transpose_kernel(const float* __restrict__ Wdec, float* __restrict__ WdecT) {
    __shared__ float tile[32][33];
    int h0 = blockIdx.x * 32;
    int d0 = blockIdx.y * 32;
    int tx = threadIdx.x, ty = threadIdx.y;
#pragma unroll
    for (int j = 0; j < 32; j += 8)
        tile[ty + j][tx] = Wdec[(size_t)(d0 + ty + j) * DHID + h0 + tx];
    __syncthreads();
#pragma unroll
    for (int j = 0; j < 32; j += 8)
        WdecT[(size_t)(h0 + ty + j) * DIN + d0 + tx] = tile[tx][ty + j];
}

// ---------------- encoder: fp16 single-term HMMA GEMM + relu ----------------
// CTA 128x128, 8 warps (4x2, 32x64 warp tiles), K-tile 32, 3-stage cp.async.
#define KTILE   32
#define STAGES  3
#define TILE_B  8192
#define STAGE_B 16384
#define GEMM_SMEM (STAGES * STAGE_B)

__global__ __launch_bounds__(256, 2)
void mma_gemm_kernel(const unsigned char* __restrict__ Ah,
                     const unsigned char* __restrict__ Bh,
                     float* __restrict__ z) {
    extern __shared__ unsigned char smem[];
    const uint32_t sb = smem_u32(smem);
    const int tid = threadIdx.x;
    const int lane = tid & 31, warp = tid >> 5;
    const int wm = warp & 3, wn = warp >> 2;
    const int m0 = blockIdx.y * 128, n0 = blockIdx.x * 128;

    float acc[2][8][4];
#pragma unroll
    for (int i = 0; i < 2; i++)
#pragma unroll
        for (int j = 0; j < 8; j++)
#pragma unroll
            for (int q = 0; q < 4; q++) acc[i][j][q] = 0.f;

    auto load_stage = [&](int s, int kc) {
        const uint32_t stage = sb + s * STAGE_B;
#pragma unroll
        for (int t = 0; t < 2; t++) {
            const int r0 = t ? n0 : m0;
            const unsigned char* g = t ? Bh : Ah;
#pragma unroll
            for (int rep = 0; rep < 2; rep++) {
                const int j = tid + rep * 256;
                const int r = j >> 2, c16 = j & 3;
                const unsigned char* src = g + (((size_t)(r0 + r) << 10) + kc * 32 + c16 * 8) * 2;
                cp16(stage + t * TILE_B + swz(r, c16), src);
            }
        }
    };

    load_stage(0, 0); CP_COMMIT();
    load_stage(1, 1); CP_COMMIT();

    for (int kc = 0; kc < DIN / KTILE; kc++) {
        if (kc + 2 < DIN / KTILE) load_stage((kc + 2) % STAGES, kc + 2);
        CP_COMMIT();
        CP_WAIT2();
        __syncthreads();
        const uint32_t stage = sb + (kc % STAGES) * STAGE_B;

#pragma unroll
        for (int ks = 0; ks < 2; ks++) {
            uint32_t ah[2][4], bh[8][2];
#pragma unroll
            for (int i = 0; i < 2; i++) {
                const int row = wm * 32 + i * 16 + (lane & 15);
                const int c16 = ks * 2 + (lane >> 4);
                ldm4(ah[i], stage + swz(row, c16));
            }
#pragma unroll
            for (int g = 0; g < 4; g++) {
                const int row = wn * 64 + g * 16 + (lane & 7) + ((lane >> 4) << 3);
                const int c16 = ks * 2 + ((lane >> 3) & 1);
                uint32_t d[4];
                ldm4(d, stage + TILE_B + swz(row, c16));
                bh[2 * g][0] = d[0]; bh[2 * g][1] = d[1];
                bh[2 * g + 1][0] = d[2]; bh[2 * g + 1][1] = d[3];
            }
#pragma unroll
            for (int i = 0; i < 2; i++)
#pragma unroll
                for (int j = 0; j < 8; j++)
                    mma_f16(acc[i][j], ah[i], bh[j]);
        }
        __syncthreads();
    }

    // epilogue: relu + store
    const int mbase = m0 + wm * 32, nbase = n0 + wn * 64;
#pragma unroll
    for (int i = 0; i < 2; i++)
#pragma unroll
        for (int j = 0; j < 8; j++) {
            const int r = mbase + i * 16 + (lane >> 2);
            const int c = nbase + j * 8 + (lane & 3) * 2;
            float2 v0, v1;
            v0.x = fmaxf(acc[i][j][0], 0.f); v0.y = fmaxf(acc[i][j][1], 0.f);
            v1.x = fmaxf(acc[i][j][2], 0.f); v1.y = fmaxf(acc[i][j][3], 0.f);
            *(float2*)(z + (size_t)r * DHID + c) = v0;
            *(float2*)(z + (size_t)(r + 8) * DHID + c) = v1;
        }
}

// ---------------- top-k stage 1: radix-select + band + fused dense z_sp -----
// Band M widened to 1e-3 (~7 sigma of the fp16 GEMM error).
__global__ void topk_kernel(const float* __restrict__ z, float* __restrict__ z_sp) {
    extern __shared__ unsigned sbuf[];
    __shared__ int hist[2048];
    __shared__ unsigned s_prefix;
    __shared__ int s_need;
    __shared__ int sureCnt, bandCnt;

    const int row = blockIdx.x, t = threadIdx.x;
    const float* zr = z + (size_t)row * DHID;

    for (int i = t; i < DHID; i += 256) sbuf[i] = __float_as_uint(zr[i]);
    if (t == 0) { sureCnt = 0; bandCnt = 0; }
    __syncthreads();

    unsigned prefix = 0;
    int curShift = 32;
    int need = TOPK;
    const int SH[4] = {21, 13, 5, 0};

#pragma unroll
    for (int l = 0; l < 4; l++) {
        const int shift = SH[l];
        const int nb = 1 << (curShift - shift);
        for (int i = t; i < nb; i += 256) hist[i] = 0;
        __syncthreads();
        for (int i = t; i < DHID; i += 256) {
            unsigned b = sbuf[i];
            if (curShift >= 32 || (b >> curShift) == prefix)
                atomicAdd(&hist[(b >> shift) & (nb - 1)], 1);
        }
        __syncthreads();
        if (t == 0) {
            int nd = need, bb;
            for (bb = nb - 1; bb > 0; bb--) {
                int c = hist[bb];
                if (c >= nd) break;
                nd -= c;
            }
            s_prefix = (prefix << (curShift - shift)) | (unsigned)bb;
            s_need = nd;
        }
        __syncthreads();
        prefix = s_prefix;
        need = s_need;
        curShift = shift;
        __syncthreads();
    }

    const float Tf = __uint_as_float(prefix);
    const float M  = 1e-3f;
    const float hi = Tf + M, lo = Tf - M;

    // record sure / band
    for (int i = t; i < DHID; i += 256) {
        float v = __uint_as_float(sbuf[i]);
        if (v > hi) {
            int s = atomicAdd(&sureCnt, 1);
            g_vals[row * TOPK + s] = v;
            g_idxs[row * TOPK + s] = i;
        } else if (v >= lo) {
            int e = atomicAdd(&bandCnt, 1);
            if (e < BANDCAP) g_band_idx[row * BANDCAP + e] = i;
        }
    }
    __syncthreads();

    // fused dense z_sparse write: sure values, zeros elsewhere (band winners
    // are patched by refine_kernel)
    float4* zo = (float4*)(z_sp + (size_t)row * DHID);
    for (int q = t; q < DHID / 4; q += 256) {
        uint4 b4 = ((const uint4*)sbuf)[q];
        float4 o;
        float v;
        v = __uint_as_float(b4.x); o.x = (v > hi) ? v : 0.f;
        v = __uint_as_float(b4.y); o.y = (v > hi) ? v : 0.f;
        v = __uint_as_float(b4.z); o.z = (v > hi) ? v : 0.f;
        v = __uint_as_float(b4.w); o.w = (v > hi) ? v : 0.f;
        zo[q] = o;
    }
    if (t == 0) {
        g_sure_cnt[row] = sureCnt;
        g_band_cnt[row] = min(bandCnt, BANDCAP);
    }
}

// ---------------- top-k stage 2: fp64 band refinement ------------------------
__global__ void refine_kernel(const float* __restrict__ z,
                              const float* __restrict__ x,
                              const float* __restrict__ Wenc,
                              float* __restrict__ z_sp) {
    __shared__ double sc[BANDCAP];
    __shared__ int   bidx[BANDCAP];
    __shared__ float bval[BANDCAP];

    const int row = blockIdx.x, t = threadIdx.x;
    const int sure = g_sure_cnt[row];
    const int bc   = g_band_cnt[row];
    const int need = TOPK - sure;

    if (t < bc) {
        int ix = g_band_idx[row * BANDCAP + t];
        bidx[t] = ix;
        bval[t] = z[(size_t)row * DHID + ix];
    }
    __syncthreads();

    if (bc > need) {   // contested: exact fp64 ranking
        const int wd = t >> 5, lane = t & 31;
        const float* xr = x + (size_t)row * DIN;
        for (int c = wd; c < bc; c += 4) {
            const float* wr = Wenc + (size_t)bidx[c] * DIN;
            double s = 0.0;
            for (int j = lane; j < DIN; j += 32)
                s += (double)xr[j] * (double)wr[j];
#pragma unroll
            for (int o = 16; o; o >>= 1)
                s += __shfl_down_sync(0xffffffffu, s, o);
            if (lane == 0) sc[c] = s;
        }
    }
    __syncthreads();

    if (t == 0) {
        int nsel = 0;
        int sel[BANDCAP];
        if (bc <= need) {
            for (int c = 0; c < bc; c++) sel[nsel++] = c;
        } else {
            bool taken[BANDCAP];
            for (int c = 0; c < bc; c++) taken[c] = false;
            for (int r = 0; r < need; r++) {
                int best = -1;
                for (int c = 0; c < bc; c++) {
                    if (taken[c]) continue;
                    if (best < 0 || sc[c] > sc[best] ||
                        (sc[c] == sc[best] && bidx[c] < bidx[best])) best = c;
                }
                taken[best] = true;
                sel[nsel++] = best;
            }
        }
        for (int a = 0; a < nsel; a++) {
            int c = sel[a];
            g_vals[row * TOPK + sure + a] = bval[c];
            g_idxs[row * TOPK + sure + a] = bidx[c];
            z_sp[(size_t)row * DHID + bidx[c]] = bval[c];
        }
        for (int a = sure + nsel; a < TOPK; a++) {
            g_vals[row * TOPK + a] = 0.f;
            g_idxs[row * TOPK + a] = 0;
        }
        for (int a = 1; a < TOPK; a++) {
            float v = g_vals[row * TOPK + a];
            int   ix = g_idxs[row * TOPK + a];
            int b = a - 1;
            while (b >= 0 && g_idxs[row * TOPK + b] > ix) {
                g_vals[row * TOPK + b + 1] = g_vals[row * TOPK + b];
                g_idxs[row * TOPK + b + 1] = g_idxs[row * TOPK + b];
                b--;
            }
            g_vals[row * TOPK + b + 1] = v;
            g_idxs[row * TOPK + b + 1] = ix;
        }
        int pos = 0;
        for (int a = 0; a < TOPK; a++)
            if (g_vals[row * TOPK + a] > 0.f) pos++;
        atomicAdd(&g_pos, pos);
    }
}

// ---------------- decoder ----------------
__global__ void decoder_kernel(const float* __restrict__ WdecT, float* __restrict__ xhat) {
    __shared__ float sv[TOPK];
    __shared__ int   si[TOPK];
    const int row = blockIdx.x, t = threadIdx.x;
    if (t < TOPK) { sv[t] = g_vals[row * TOPK + t]; si[t] = g_idxs[row * TOPK + t]; }
    __syncthreads();
    const int d = t * 4;
    float x0 = 0.f, x1 = 0.f, x2 = 0.f, x3 = 0.f;
#pragma unroll
    for (int k = 0; k < TOPK; k++) {
        float v = sv[k];
        const float4 w = *(const float4*)(WdecT + (size_t)si[k] * DIN + d);
        x0 += v * w.x; x1 += v * w.y; x2 += v * w.z; x3 += v * w.w;
    }
    *(float4*)(xhat + (size_t)row * DIN + d) = make_float4(x0, x1, x2, x3);
}

// ---------------- active ----------------
__global__ void finalize_kernel(float* __restrict__ act) {
    *act = (float)g_pos / (float)NROWS;
}

// ---------------- launch ----------------
extern "C" void kernel_launch(void* const* d_in, const int* in_sizes, int n_in,
                              void* d_out, int out_size) {
    const float* x     = (const float*)d_in[0];
    const float* W_enc = (const float*)d_in[1];
    const float* W_dec = (const float*)d_in[2];
    float* out = (float*)d_out;

    float* xhat = out + OFF_XHAT;
    float* z_sp = out + OFF_ZSP;
    float* z    = out + OFF_Z;
    float* act  = out + OFF_ACT;

    float* WdecT;
    cudaGetSymbolAddress((void**)&WdecT, g_WdecT);
    unsigned char *xh, *wh;
    cudaGetSymbolAddress((void**)&xh, g_xh);
    cudaGetSymbolAddress((void**)&wh, g_wh);

    cudaFuncSetAttribute(topk_kernel, cudaFuncAttributeMaxDynamicSharedMemorySize, 65536);
    cudaFuncSetAttribute(mma_gemm_kernel, cudaFuncAttributeMaxDynamicSharedMemorySize, GEMM_SMEM);

    reset_kernel<<<1, 1>>>();
    packh_kernel<<<(NROWS * DIN / 2 + 255) / 256, 256>>>(x, (unsigned*)xh, NROWS * DIN / 2);
    packh_kernel<<<(DHID * DIN / 2 + 255) / 256, 256>>>(W_enc, (unsigned*)wh, DHID * DIN / 2);
    transpose_kernel<<<dim3(DHID / 32, DIN / 32), dim3(32, 8)>>>(W_dec, WdecT);
    mma_gemm_kernel<<<dim3(DHID / 128, NROWS / 128), 256, GEMM_SMEM>>>(xh, wh, z);
    topk_kernel<<<NROWS, 256, 65536>>>(z, z_sp);
    refine_kernel<<<NROWS, 128>>>(z, x, W_enc, z_sp);
    decoder_kernel<<<NROWS, 256>>>(WdecT, xhat);
    finalize_kernel<<<1, 1>>>(act);
}

// round 8
// speedup vs baseline: 3.6118x; 1.2482x over previous
#include <cuda_runtime.h>
#include <cuda_bf16.h>
#include <cuda_fp16.h>
#include <cstdint>

// Problem constants
#define NROWS   8192
#define DIN     1024
#define DHID    16384
#define TOPK    32
#define BANDCAP 64
#define CAP     1024          // candidate buffer per row
#define TAU     0.78f         // static candidate threshold (~2.3 sigma)
#define BANDM   1e-3f         // refinement band half-width

// Output layout:
//   x_hat    [8192,1024]   @ 0
//   z_sparse [8192,16384]  @ 8388608
//   z        [8192,16384]  @ 142606336
//   active   scalar        @ 276824064
#define OFF_XHAT   0
#define OFF_ZSP    8388608
#define OFF_Z      142606336
#define OFF_ACT    276824064

// -------- device scratch (no allocations allowed) --------
__device__ float g_WdecT[(size_t)DHID * DIN];                                // 64 MB
__device__ __align__(256) unsigned char g_xh[(size_t)NROWS * DIN * 2];       // fp16 x
__device__ __align__(256) unsigned char g_wh[(size_t)DHID * DIN * 2];        // fp16 W_enc
__device__ uint2 g_cand[(size_t)NROWS * CAP];                                // 64 MB (valbits, idx)
__device__ int   g_cand_cnt[NROWS];
__device__ float g_vals[NROWS * TOPK];
__device__ int   g_idxs[NROWS * TOPK];
__device__ int   g_band_idx[NROWS * BANDCAP];
__device__ int   g_band_cnt[NROWS];
__device__ int   g_sure_cnt[NROWS];
__device__ int   g_pos;

// ---------------- PTX helpers (baseline compute_103 feature set only) -------
__device__ __forceinline__ uint32_t smem_u32(const void* p) {
    uint32_t a;
    asm("{ .reg .u64 t; cvta.to.shared.u64 t, %1; cvt.u32.u64 %0, t; }" : "=r"(a) : "l"(p));
    return a;
}
__device__ __forceinline__ void cp16(uint32_t dst, const void* src) {
    asm volatile("cp.async.cg.shared.global [%0], [%1], 16;" :: "r"(dst), "l"(src));
}
#define CP_COMMIT() asm volatile("cp.async.commit_group;" ::: "memory")
#define CP_WAIT1()  asm volatile("cp.async.wait_group 1;" ::: "memory")

__device__ __forceinline__ void ldm4(uint32_t* d, uint32_t addr) {
    asm volatile("ldmatrix.sync.aligned.m8n8.x4.shared.b16 {%0,%1,%2,%3}, [%4];"
        : "=r"(d[0]), "=r"(d[1]), "=r"(d[2]), "=r"(d[3]) : "r"(addr));
}
__device__ __forceinline__ void mma_f16(float* c, const uint32_t* a, const uint32_t* b) {
    asm volatile("mma.sync.aligned.m16n8k16.row.col.f32.f16.f16.f32 "
        "{%0,%1,%2,%3}, {%4,%5,%6,%7}, {%8,%9}, {%0,%1,%2,%3};"
        : "+f"(c[0]), "+f"(c[1]), "+f"(c[2]), "+f"(c[3])
        : "r"(a[0]), "r"(a[1]), "r"(a[2]), "r"(a[3]), "r"(b[0]), "r"(b[1]));
}

// conflict-free chunk swizzle for 64B rows
__device__ __forceinline__ uint32_t swz(int r, int c16) {
    return (uint32_t)(r * 64 + ((c16 ^ ((r >> 1) & 3)) << 4));
}

// ---------------- reset: g_pos + candidate counters ----------------
__global__ void reset_kernel() {
    int i = blockIdx.x * blockDim.x + threadIdx.x;
    if (i < NROWS) g_cand_cnt[i] = 0;
    if (i == 0) g_pos = 0;
}

// ---------------- zero-fill z_sparse ----------------
__global__ void fill0_kernel(float4* __restrict__ p) {
    int i = blockIdx.x * blockDim.x + threadIdx.x;
    p[i] = make_float4(0.f, 0.f, 0.f, 0.f);
}

// ---------------- pack: fp32 -> fp16 ----------------------------------------
__global__ void packh_kernel(const float* __restrict__ src, unsigned* __restrict__ dst, int n2) {
    int i = blockIdx.x * blockDim.x + threadIdx.x;
    if (i >= n2) return;
    float2 v = ((const float2*)src)[i];
    __half2 h = __floats2half2_rn(v.x, v.y);
    dst[i] = *reinterpret_cast<unsigned*>(&h);
}

// ---------------- W_dec transpose ----------------
__global__ void transpose_kernel(const float* __restrict__ Wdec, float* __restrict__ WdecT) {
    __shared__ float tile[32][33];
    int h0 = blockIdx.x * 32;
    int d0 = blockIdx.y * 32;
    int tx = threadIdx.x, ty = threadIdx.y;
#pragma unroll
    for (int j = 0; j < 32; j += 8)
        tile[ty + j][tx] = Wdec[(size_t)(d0 + ty + j) * DHID + h0 + tx];
    __syncthreads();
#pragma unroll
    for (int j = 0; j < 32; j += 8)
        WdecT[(size_t)(h0 + ty + j) * DIN + d0 + tx] = tile[tx][ty + j];
}

// ---------------- encoder: fp16 HMMA GEMM + relu + candidate pre-filter -----
#define KTILE   32
#define STAGES  3
#define TILE_B  8192
#define STAGE_B 16384
#define GEMM_SMEM (STAGES * STAGE_B)

__global__ __launch_bounds__(256, 2)
void mma_gemm_kernel(const unsigned char* __restrict__ Ah,
                     const unsigned char* __restrict__ Bh,
                     float* __restrict__ z) {
    extern __shared__ unsigned char smem[];
    const uint32_t sb = smem_u32(smem);
    const int tid = threadIdx.x;
    const int lane = tid & 31, warp = tid >> 5;
    const int wm = warp & 3, wn = warp >> 2;
    const int m0 = blockIdx.y * 128, n0 = blockIdx.x * 128;

    float acc[2][8][4];
#pragma unroll
    for (int i = 0; i < 2; i++)
#pragma unroll
        for (int j = 0; j < 8; j++)
#pragma unroll
            for (int q = 0; q < 4; q++) acc[i][j][q] = 0.f;

    auto load_stage = [&](int s, int kc) {
        const uint32_t stage = sb + s * STAGE_B;
#pragma unroll
        for (int t = 0; t < 2; t++) {
            const int r0 = t ? n0 : m0;
            const unsigned char* g = t ? Bh : Ah;
#pragma unroll
            for (int rep = 0; rep < 2; rep++) {
                const int j = tid + rep * 256;
                const int r = j >> 2, c16 = j & 3;
                const unsigned char* src = g + (((size_t)(r0 + r) << 10) + kc * 32 + c16 * 8) * 2;
                cp16(stage + t * TILE_B + swz(r, c16), src);
            }
        }
    };

    load_stage(0, 0); CP_COMMIT();
    load_stage(1, 1); CP_COMMIT();

    for (int kc = 0; kc < DIN / KTILE; kc++) {
        CP_WAIT1();                      // stage kc's data complete
        __syncthreads();                 // visible to all; prior stage reads done
        if (kc + 2 < DIN / KTILE) load_stage((kc + 2) % STAGES, kc + 2);
        CP_COMMIT();
        const uint32_t stage = sb + (kc % STAGES) * STAGE_B;

#pragma unroll
        for (int ks = 0; ks < 2; ks++) {
            uint32_t ah[2][4], bh[8][2];
#pragma unroll
            for (int i = 0; i < 2; i++) {
                const int row = wm * 32 + i * 16 + (lane & 15);
                const int c16 = ks * 2 + (lane >> 4);
                ldm4(ah[i], stage + swz(row, c16));
            }
#pragma unroll
            for (int g = 0; g < 4; g++) {
                const int row = wn * 64 + g * 16 + (lane & 7) + ((lane >> 4) << 3);
                const int c16 = ks * 2 + ((lane >> 3) & 1);
                uint32_t d[4];
                ldm4(d, stage + TILE_B + swz(row, c16));
                bh[2 * g][0] = d[0]; bh[2 * g][1] = d[1];
                bh[2 * g + 1][0] = d[2]; bh[2 * g + 1][1] = d[3];
            }
#pragma unroll
            for (int i = 0; i < 2; i++)
#pragma unroll
                for (int j = 0; j < 8; j++)
                    mma_f16(acc[i][j], ah[i], bh[j]);
        }
        __syncthreads();
    }

    // epilogue: relu + store + candidate push (v > TAU)
    const int mbase = m0 + wm * 32, nbase = n0 + wn * 64;
#pragma unroll
    for (int i = 0; i < 2; i++)
#pragma unroll
        for (int j = 0; j < 8; j++) {
            const int r = mbase + i * 16 + (lane >> 2);
            const int c = nbase + j * 8 + (lane & 3) * 2;
            float2 v0, v1;
            v0.x = fmaxf(acc[i][j][0], 0.f); v0.y = fmaxf(acc[i][j][1], 0.f);
            v1.x = fmaxf(acc[i][j][2], 0.f); v1.y = fmaxf(acc[i][j][3], 0.f);
            *(float2*)(z + (size_t)r * DHID + c) = v0;
            *(float2*)(z + (size_t)(r + 8) * DHID + c) = v1;
            if (v0.x > TAU) { int s = atomicAdd(&g_cand_cnt[r], 1);
                if (s < CAP) g_cand[(size_t)r * CAP + s] = make_uint2(__float_as_uint(v0.x), c); }
            if (v0.y > TAU) { int s = atomicAdd(&g_cand_cnt[r], 1);
                if (s < CAP) g_cand[(size_t)r * CAP + s] = make_uint2(__float_as_uint(v0.y), c + 1); }
            if (v1.x > TAU) { int s = atomicAdd(&g_cand_cnt[r + 8], 1);
                if (s < CAP) g_cand[(size_t)(r + 8) * CAP + s] = make_uint2(__float_as_uint(v1.x), c); }
            if (v1.y > TAU) { int s = atomicAdd(&g_cand_cnt[r + 8], 1);
                if (s < CAP) g_cand[(size_t)(r + 8) * CAP + s] = make_uint2(__float_as_uint(v1.y), c + 1); }
        }
}

// ---------------- top-k (fast path): rank-select over candidates ------------
__global__ void topk_small_kernel(float* __restrict__ z_sp) {
    __shared__ float cv[CAP];
    __shared__ int   ci[CAP];
    __shared__ float sT;
    __shared__ int sureCnt, bandCnt;

    const int row = blockIdx.x, t = threadIdx.x;   // 256 threads
    const int cnt = g_cand_cnt[row];
    if (cnt < 48 || cnt > CAP) return;             // fallback kernel handles

    for (int i = t; i < cnt; i += 256) {
        uint2 p = g_cand[(size_t)row * CAP + i];
        cv[i] = __uint_as_float(p.x);
        ci[i] = (int)p.y;
    }
    if (t == 0) { sureCnt = 0; bandCnt = 0; }
    __syncthreads();

    // exact rank under strict total order (value desc, index asc)
    for (int c = t; c < cnt; c += 256) {
        float v = cv[c]; int ix = ci[c];
        int rank = 0;
        for (int j = 0; j < cnt; j++) {
            float u = cv[j];
            rank += (u > v) || (u == v && ci[j] < ix);
        }
        if (rank == TOPK - 1) sT = v;              // our 32nd-largest
    }
    __syncthreads();

    const float T = sT, hi = T + BANDM, lo = T - BANDM;
    for (int c = t; c < cnt; c += 256) {
        float v = cv[c];
        if (v > hi) {
            int s = atomicAdd(&sureCnt, 1);
            g_vals[row * TOPK + s] = v;
            g_idxs[row * TOPK + s] = ci[c];
            z_sp[(size_t)row * DHID + ci[c]] = v;
        } else if (v >= lo) {
            int e = atomicAdd(&bandCnt, 1);
            if (e < BANDCAP) g_band_idx[row * BANDCAP + e] = ci[c];
        }
    }
    __syncthreads();
    if (t == 0) {
        g_sure_cnt[row] = sureCnt;
        g_band_cnt[row] = min(bandCnt, BANDCAP);
    }
}

// ---------------- top-k (fallback): full radix scan, rare/never --------------
__global__ void fallback_kernel(const float* __restrict__ z, float* __restrict__ z_sp) {
    __shared__ int hist[2048];
    __shared__ unsigned s_prefix;
    __shared__ int s_need;
    __shared__ int sureCnt, bandCnt;

    const int row = blockIdx.x, t = threadIdx.x;
    const int cnt = g_cand_cnt[row];
    if (cnt >= 48 && cnt <= CAP) return;           // fast path handled it

    const float* zr = z + (size_t)row * DHID;
    if (t == 0) { sureCnt = 0; bandCnt = 0; }
    __syncthreads();

    unsigned prefix = 0;
    int curShift = 32;
    int need = TOPK;
    const int SH[4] = {21, 13, 5, 0};

#pragma unroll
    for (int l = 0; l < 4; l++) {
        const int shift = SH[l];
        const int nb = 1 << (curShift - shift);
        for (int i = t; i < nb; i += 256) hist[i] = 0;
        __syncthreads();
        for (int i = t; i < DHID; i += 256) {
            unsigned b = __float_as_uint(zr[i]);
            if (curShift >= 32 || (b >> curShift) == prefix)
                atomicAdd(&hist[(b >> shift) & (nb - 1)], 1);
        }
        __syncthreads();
        if (t == 0) {
            int nd = need, bb;
            for (bb = nb - 1; bb > 0; bb--) {
                int c = hist[bb];
                if (c >= nd) break;
                nd -= c;
            }
            s_prefix = (prefix << (curShift - shift)) | (unsigned)bb;
            s_need = nd;
        }
        __syncthreads();
        prefix = s_prefix;
        need = s_need;
        curShift = shift;
        __syncthreads();
    }

    const float Tf = __uint_as_float(prefix);
    const float hi = Tf + BANDM, lo = Tf - BANDM;

    for (int i = t; i < DHID; i += 256) {
        float v = zr[i];
        if (v > hi) {
            int s = atomicAdd(&sureCnt, 1);
            g_vals[row * TOPK + s] = v;
            g_idxs[row * TOPK + s] = i;
            z_sp[(size_t)row * DHID + i] = v;
        } else if (v >= lo) {
            int e = atomicAdd(&bandCnt, 1);
            if (e < BANDCAP) g_band_idx[row * BANDCAP + e] = i;
        }
    }
    __syncthreads();
    if (t == 0) {
        g_sure_cnt[row] = sureCnt;
        g_band_cnt[row] = min(bandCnt, BANDCAP);
    }
}

// ---------------- top-k stage 2: fp64 band refinement ------------------------
__global__ void refine_kernel(const float* __restrict__ z,
                              const float* __restrict__ x,
                              const float* __restrict__ Wenc,
                              float* __restrict__ z_sp) {
    __shared__ double sc[BANDCAP];
    __shared__ int   bidx[BANDCAP];
    __shared__ float bval[BANDCAP];

    const int row = blockIdx.x, t = threadIdx.x;
    const int sure = g_sure_cnt[row];
    const int bc   = g_band_cnt[row];
    const int need = TOPK - sure;

    if (t < bc) {
        int ix = g_band_idx[row * BANDCAP + t];
        bidx[t] = ix;
        bval[t] = z[(size_t)row * DHID + ix];
    }
    __syncthreads();

    if (bc > need) {   // contested: exact fp64 ranking
        const int wd = t >> 5, lane = t & 31;
        const float* xr = x + (size_t)row * DIN;
        for (int c = wd; c < bc; c += 4) {
            const float* wr = Wenc + (size_t)bidx[c] * DIN;
            double s = 0.0;
            for (int j = lane; j < DIN; j += 32)
                s += (double)xr[j] * (double)wr[j];
#pragma unroll
            for (int o = 16; o; o >>= 1)
                s += __shfl_down_sync(0xffffffffu, s, o);
            if (lane == 0) sc[c] = s;
        }
    }
    __syncthreads();

    if (t == 0) {
        int nsel = 0;
        int sel[BANDCAP];
        if (bc <= need) {
            for (int c = 0; c < bc; c++) sel[nsel++] = c;
        } else {
            bool taken[BANDCAP];
            for (int c = 0; c < bc; c++) taken[c] = false;
            for (int r = 0; r < need; r++) {
                int best = -1;
                for (int c = 0; c < bc; c++) {
                    if (taken[c]) continue;
                    if (best < 0 || sc[c] > sc[best] ||
                        (sc[c] == sc[best] && bidx[c] < bidx[best])) best = c;
                }
                taken[best] = true;
                sel[nsel++] = best;
            }
        }
        for (int a = 0; a < nsel; a++) {
            int c = sel[a];
            g_vals[row * TOPK + sure + a] = bval[c];
            g_idxs[row * TOPK + sure + a] = bidx[c];
            z_sp[(size_t)row * DHID + bidx[c]] = bval[c];
        }
        for (int a = sure + nsel; a < TOPK; a++) {
            g_vals[row * TOPK + a] = 0.f;
            g_idxs[row * TOPK + a] = 0;
        }
        for (int a = 1; a < TOPK; a++) {
            float v = g_vals[row * TOPK + a];
            int   ix = g_idxs[row * TOPK + a];
            int b = a - 1;
            while (b >= 0 && g_idxs[row * TOPK + b] > ix) {
                g_vals[row * TOPK + b + 1] = g_vals[row * TOPK + b];
                g_idxs[row * TOPK + b + 1] = g_idxs[row * TOPK + b];
                b--;
            }
            g_vals[row * TOPK + b + 1] = v;
            g_idxs[row * TOPK + b + 1] = ix;
        }
        int pos = 0;
        for (int a = 0; a < TOPK; a++)
            if (g_vals[row * TOPK + a] > 0.f) pos++;
        atomicAdd(&g_pos, pos);
    }
}

// ---------------- decoder ----------------
__global__ void decoder_kernel(const float* __restrict__ WdecT, float* __restrict__ xhat) {
    __shared__ float sv[TOPK];
    __shared__ int   si[TOPK];
    const int row = blockIdx.x, t = threadIdx.x;
    if (t < TOPK) { sv[t] = g_vals[row * TOPK + t]; si[t] = g_idxs[row * TOPK + t]; }
    __syncthreads();
    const int d = t * 4;
    float x0 = 0.f, x1 = 0.f, x2 = 0.f, x3 = 0.f;
#pragma unroll
    for (int k = 0; k < TOPK; k++) {
        float v = sv[k];
        const float4 w = *(const float4*)(WdecT + (size_t)si[k] * DIN + d);
        x0 += v * w.x; x1 += v * w.y; x2 += v * w.z; x3 += v * w.w;
    }
    *(float4*)(xhat + (size_t)row * DIN + d) = make_float4(x0, x1, x2, x3);
}

// ---------------- active ----------------
__global__ void finalize_kernel(float* __restrict__ act) {
    *act = (float)g_pos / (float)NROWS;
}

// ---------------- launch ----------------
extern "C" void kernel_launch(void* const* d_in, const int* in_sizes, int n_in,
                              void* d_out, int out_size) {
    const float* x     = (const float*)d_in[0];
    const float* W_enc = (const float*)d_in[1];
    const float* W_dec = (const float*)d_in[2];
    float* out = (float*)d_out;

    float* xhat = out + OFF_XHAT;
    float* z_sp = out + OFF_ZSP;
    float* z    = out + OFF_Z;
    float* act  = out + OFF_ACT;

    float* WdecT;
    cudaGetSymbolAddress((void**)&WdecT, g_WdecT);
    unsigned char *xh, *wh;
    cudaGetSymbolAddress((void**)&xh, g_xh);
    cudaGetSymbolAddress((void**)&wh, g_wh);

    cudaFuncSetAttribute(mma_gemm_kernel, cudaFuncAttributeMaxDynamicSharedMemorySize, GEMM_SMEM);

    reset_kernel<<<NROWS / 256, 256>>>();
    fill0_kernel<<<131072, 256>>>((float4*)z_sp);
    packh_kernel<<<(NROWS * DIN / 2 + 255) / 256, 256>>>(x, (unsigned*)xh, NROWS * DIN / 2);
    packh_kernel<<<(DHID * DIN / 2 + 255) / 256, 256>>>(W_enc, (unsigned*)wh, DHID * DIN / 2);
    transpose_kernel<<<dim3(DHID / 32, DIN / 32), dim3(32, 8)>>>(W_dec, WdecT);
    mma_gemm_kernel<<<dim3(DHID / 128, NROWS / 128), 256, GEMM_SMEM>>>(xh, wh, z);
    topk_small_kernel<<<NROWS, 256>>>(z_sp);
    fallback_kernel<<<NROWS, 256>>>(z, z_sp);
    refine_kernel<<<NROWS, 128>>>(z, x, W_enc, z_sp);
    decoder_kernel<<<NROWS, 256>>>(WdecT, xhat);
    finalize_kernel<<<1, 1>>>(act);
}

// round 10
// speedup vs baseline: 5.5982x; 1.5500x over previous
#include <cuda_runtime.h>
#include <cuda_bf16.h>
#include <cuda_fp16.h>
#include <cstdint>

// Problem constants
#define NROWS   8192
#define DIN     1024
#define DHID    16384
#define TOPK    32
#define BANDCAP 64
#define CAP     1024          // candidate buffer per row
#define TAU     0.78f         // static candidate threshold (~2.3 sigma)
#define BANDM   1e-3f         // refinement band half-width

// Output layout:
//   x_hat    [8192,1024]   @ 0
//   z_sparse [8192,16384]  @ 8388608
//   z        [8192,16384]  @ 142606336
//   active   scalar        @ 276824064
#define OFF_XHAT   0
#define OFF_ZSP    8388608
#define OFF_Z      142606336
#define OFF_ACT    276824064

// -------- device scratch (no allocations allowed) --------
__device__ float g_WdecT[(size_t)DHID * DIN];                                // 64 MB
__device__ __align__(256) unsigned char g_xh[(size_t)NROWS * DIN * 2];       // fp16 x
__device__ __align__(256) unsigned char g_wh[(size_t)DHID * DIN * 2];        // fp16 W_enc
__device__ uint2 g_cand[(size_t)NROWS * CAP];                                // 64 MB (valbits, idx)
__device__ int   g_cand_cnt[NROWS];
__device__ float g_vals[NROWS * TOPK];
__device__ int   g_idxs[NROWS * TOPK];
__device__ int   g_pos;

// ---------------- PTX helpers (baseline compute_103 feature set only) -------
__device__ __forceinline__ uint32_t smem_u32(const void* p) {
    uint32_t a;
    asm("{ .reg .u64 t; cvta.to.shared.u64 t, %1; cvt.u32.u64 %0, t; }" : "=r"(a) : "l"(p));
    return a;
}
__device__ __forceinline__ void cp16(uint32_t dst, const void* src) {
    asm volatile("cp.async.cg.shared.global [%0], [%1], 16;" :: "r"(dst), "l"(src));
}
#define CP_COMMIT() asm volatile("cp.async.commit_group;" ::: "memory")
#define CP_WAIT1()  asm volatile("cp.async.wait_group 1;" ::: "memory")

__device__ __forceinline__ void ldm4(uint32_t* d, uint32_t addr) {
    asm volatile("ldmatrix.sync.aligned.m8n8.x4.shared.b16 {%0,%1,%2,%3}, [%4];"
        : "=r"(d[0]), "=r"(d[1]), "=r"(d[2]), "=r"(d[3]) : "r"(addr));
}
__device__ __forceinline__ void mma_f16(float* c, const uint32_t* a, const uint32_t* b) {
    asm volatile("mma.sync.aligned.m16n8k16.row.col.f32.f16.f16.f32 "
        "{%0,%1,%2,%3}, {%4,%5,%6,%7}, {%8,%9}, {%0,%1,%2,%3};"
        : "+f"(c[0]), "+f"(c[1]), "+f"(c[2]), "+f"(c[3])
        : "r"(a[0]), "r"(a[1]), "r"(a[2]), "r"(a[3]), "r"(b[0]), "r"(b[1]));
}

// conflict-free chunk swizzle for 64B rows
__device__ __forceinline__ uint32_t swz(int r, int c16) {
    return (uint32_t)(r * 64 + ((c16 ^ ((r >> 1) & 3)) << 4));
}

// ---------------- reset: g_pos + candidate counters ----------------
__global__ void reset_kernel() {
    int i = blockIdx.x * blockDim.x + threadIdx.x;
    if (i < NROWS) g_cand_cnt[i] = 0;
    if (i == 0) g_pos = 0;
}

// ---------------- pack: fp32 -> fp16, 8 elems/thread -------------------------
__global__ void packh_kernel(const float4* __restrict__ src, uint4* __restrict__ dst, int n8) {
    int i = blockIdx.x * blockDim.x + threadIdx.x;
    if (i >= n8) return;
    float4 a = src[2 * i], b = src[2 * i + 1];
    __half2 h0 = __floats2half2_rn(a.x, a.y);
    __half2 h1 = __floats2half2_rn(a.z, a.w);
    __half2 h2 = __floats2half2_rn(b.x, b.y);
    __half2 h3 = __floats2half2_rn(b.z, b.w);
    uint4 o;
    o.x = *reinterpret_cast<unsigned*>(&h0);
    o.y = *reinterpret_cast<unsigned*>(&h1);
    o.z = *reinterpret_cast<unsigned*>(&h2);
    o.w = *reinterpret_cast<unsigned*>(&h3);
    dst[i] = o;
}

// ---------------- W_dec transpose ----------------
__global__ void transpose_kernel(const float* __restrict__ Wdec, float* __restrict__ WdecT) {
    __shared__ float tile[32][33];
    int h0 = blockIdx.x * 32;
    int d0 = blockIdx.y * 32;
    int tx = threadIdx.x, ty = threadIdx.y;
#pragma unroll
    for (int j = 0; j < 32; j += 8)
        tile[ty + j][tx] = Wdec[(size_t)(d0 + ty + j) * DHID + h0 + tx];
    __syncthreads();
#pragma unroll
    for (int j = 0; j < 32; j += 8)
        WdecT[(size_t)(h0 + ty + j) * DIN + d0 + tx] = tile[tx][ty + j];
}

// ---------------- encoder: fp16 HMMA GEMM + relu + z_sp zeros + candidates --
#define KTILE   32
#define STAGES  3
#define TILE_B  8192
#define STAGE_B 16384
#define GEMM_SMEM (STAGES * STAGE_B)

__global__ __launch_bounds__(256, 2)
void mma_gemm_kernel(const unsigned char* __restrict__ Ah,
                     const unsigned char* __restrict__ Bh,
                     float* __restrict__ z, float* __restrict__ z_sp) {
    extern __shared__ unsigned char smem[];
    const uint32_t sb = smem_u32(smem);
    const int tid = threadIdx.x;
    const int lane = tid & 31, warp = tid >> 5;
    const int wm = warp & 3, wn = warp >> 2;
    const int m0 = blockIdx.y * 128, n0 = blockIdx.x * 128;

    float acc[2][8][4];
#pragma unroll
    for (int i = 0; i < 2; i++)
#pragma unroll
        for (int j = 0; j < 8; j++)
#pragma unroll
            for (int q = 0; q < 4; q++) acc[i][j][q] = 0.f;

    auto load_stage = [&](int s, int kc) {
        const uint32_t stage = sb + s * STAGE_B;
#pragma unroll
        for (int t = 0; t < 2; t++) {
            const int r0 = t ? n0 : m0;
            const unsigned char* g = t ? Bh : Ah;
#pragma unroll
            for (int rep = 0; rep < 2; rep++) {
                const int j = tid + rep * 256;
                const int r = j >> 2, c16 = j & 3;
                const unsigned char* src = g + (((size_t)(r0 + r) << 10) + kc * 32 + c16 * 8) * 2;
                cp16(stage + t * TILE_B + swz(r, c16), src);
            }
        }
    };

    load_stage(0, 0); CP_COMMIT();
    load_stage(1, 1); CP_COMMIT();

    for (int kc = 0; kc < DIN / KTILE; kc++) {
        CP_WAIT1();                      // stage kc's data complete
        __syncthreads();                 // all threads done reading stage kc-1
        if (kc + 2 < DIN / KTILE) load_stage((kc + 2) % STAGES, kc + 2);
        CP_COMMIT();
        const uint32_t stage = sb + (kc % STAGES) * STAGE_B;

#pragma unroll
        for (int ks = 0; ks < 2; ks++) {
            uint32_t ah[2][4], bh[8][2];
#pragma unroll
            for (int i = 0; i < 2; i++) {
                const int row = wm * 32 + i * 16 + (lane & 15);
                const int c16 = ks * 2 + (lane >> 4);
                ldm4(ah[i], stage + swz(row, c16));
            }
#pragma unroll
            for (int g = 0; g < 4; g++) {
                const int row = wn * 64 + g * 16 + (lane & 7) + ((lane >> 4) << 3);
                const int c16 = ks * 2 + ((lane >> 3) & 1);
                uint32_t d[4];
                ldm4(d, stage + TILE_B + swz(row, c16));
                bh[2 * g][0] = d[0]; bh[2 * g][1] = d[1];
                bh[2 * g + 1][0] = d[2]; bh[2 * g + 1][1] = d[3];
            }
#pragma unroll
            for (int i = 0; i < 2; i++)
#pragma unroll
                for (int j = 0; j < 8; j++)
                    mma_f16(acc[i][j], ah[i], bh[j]);
        }
    }

    // epilogue: relu + z store + z_sp zero store + candidate push (v > TAU)
    const int mbase = m0 + wm * 32, nbase = n0 + wn * 64;
    const float2 zero2 = make_float2(0.f, 0.f);
#pragma unroll
    for (int i = 0; i < 2; i++)
#pragma unroll
        for (int j = 0; j < 8; j++) {
            const int r = mbase + i * 16 + (lane >> 2);
            const int c = nbase + j * 8 + (lane & 3) * 2;
            float2 v0, v1;
            v0.x = fmaxf(acc[i][j][0], 0.f); v0.y = fmaxf(acc[i][j][1], 0.f);
            v1.x = fmaxf(acc[i][j][2], 0.f); v1.y = fmaxf(acc[i][j][3], 0.f);
            *(float2*)(z + (size_t)r * DHID + c) = v0;
            *(float2*)(z + (size_t)(r + 8) * DHID + c) = v1;
            *(float2*)(z_sp + (size_t)r * DHID + c) = zero2;
            *(float2*)(z_sp + (size_t)(r + 8) * DHID + c) = zero2;
            if (v0.x > TAU) { int s = atomicAdd(&g_cand_cnt[r], 1);
                if (s < CAP) g_cand[(size_t)r * CAP + s] = make_uint2(__float_as_uint(v0.x), c); }
            if (v0.y > TAU) { int s = atomicAdd(&g_cand_cnt[r], 1);
                if (s < CAP) g_cand[(size_t)r * CAP + s] = make_uint2(__float_as_uint(v0.y), c + 1); }
            if (v1.x > TAU) { int s = atomicAdd(&g_cand_cnt[r + 8], 1);
                if (s < CAP) g_cand[(size_t)(r + 8) * CAP + s] = make_uint2(__float_as_uint(v1.x), c); }
            if (v1.y > TAU) { int s = atomicAdd(&g_cand_cnt[r + 8], 1);
                if (s < CAP) g_cand[(size_t)(r + 8) * CAP + s] = make_uint2(__float_as_uint(v1.y), c + 1); }
        }
}

// ---------------- merged selection: top-k + fallback + fp64 refine ----------
// One block (256 threads) per row. Fast path ranks the pre-filtered
// candidates; rare fallback does the dense radix scan. Band refinement
// runs inline with band data held in smem.
__global__ void select_kernel(const float* __restrict__ z,
                              const float* __restrict__ x,
                              const float* __restrict__ Wenc,
                              float* __restrict__ z_sp) {
    __shared__ float cv[CAP];
    __shared__ int   ci[CAP];
    __shared__ int   hist[2048];
    __shared__ float sT;
    __shared__ int sureCnt, bandCnt;
    __shared__ int   bidx[BANDCAP];
    __shared__ float bval[BANDCAP];
    __shared__ double sc[BANDCAP];

    const int row = blockIdx.x, t = threadIdx.x;
    const int cnt = g_cand_cnt[row];
    if (t == 0) { sureCnt = 0; bandCnt = 0; }
    __syncthreads();

    if (cnt >= 48 && cnt <= CAP) {
        // ---- fast path: rank-select over candidates ----
        for (int i = t; i < cnt; i += 256) {
            uint2 p = g_cand[(size_t)row * CAP + i];
            cv[i] = __uint_as_float(p.x);
            ci[i] = (int)p.y;
        }
        __syncthreads();

        // exact rank under strict total order (value desc, index asc)
        for (int c = t; c < cnt; c += 256) {
            float v = cv[c]; int ix = ci[c];
            int rank = 0;
            for (int j = 0; j < cnt; j++) {
                float u = cv[j];
                rank += (u > v) || (u == v && ci[j] < ix);
            }
            if (rank == TOPK - 1) sT = v;
        }
        __syncthreads();

        const float T = sT, hi = T + BANDM, lo = T - BANDM;
        for (int c = t; c < cnt; c += 256) {
            float v = cv[c];
            if (v > hi) {
                int s = atomicAdd(&sureCnt, 1);
                g_vals[row * TOPK + s] = v;
                g_idxs[row * TOPK + s] = ci[c];
                z_sp[(size_t)row * DHID + ci[c]] = v;
            } else if (v >= lo) {
                int e = atomicAdd(&bandCnt, 1);
                if (e < BANDCAP) { bidx[e] = ci[c]; bval[e] = v; }
            }
        }
    } else {
        // ---- fallback: dense radix-select over the z row ----
        const float* zr = z + (size_t)row * DHID;
        unsigned prefix = 0;
        int curShift = 32;
        int need = TOPK;
        const int SH[4] = {21, 13, 5, 0};
        __shared__ unsigned s_prefix;
        __shared__ int s_need;

#pragma unroll
        for (int l = 0; l < 4; l++) {
            const int shift = SH[l];
            const int nb = 1 << (curShift - shift);
            for (int i = t; i < nb; i += 256) hist[i] = 0;
            __syncthreads();
            for (int i = t; i < DHID; i += 256) {
                unsigned b = __float_as_uint(zr[i]);
                if (curShift >= 32 || (b >> curShift) == prefix)
                    atomicAdd(&hist[(b >> shift) & (nb - 1)], 1);
            }
            __syncthreads();
            if (t == 0) {
                int nd = need, bb;
                for (bb = nb - 1; bb > 0; bb--) {
                    int c = hist[bb];
                    if (c >= nd) break;
                    nd -= c;
                }
                s_prefix = (prefix << (curShift - shift)) | (unsigned)bb;
                s_need = nd;
            }
            __syncthreads();
            prefix = s_prefix;
            need = s_need;
            curShift = shift;
            __syncthreads();
        }

        const float Tf = __uint_as_float(prefix);
        const float hi = Tf + BANDM, lo = Tf - BANDM;
        for (int i = t; i < DHID; i += 256) {
            float v = zr[i];
            if (v > hi) {
                int s = atomicAdd(&sureCnt, 1);
                g_vals[row * TOPK + s] = v;
                g_idxs[row * TOPK + s] = i;
                z_sp[(size_t)row * DHID + i] = v;
            } else if (v >= lo) {
                int e = atomicAdd(&bandCnt, 1);
                if (e < BANDCAP) { bidx[e] = i; bval[e] = v; }
            }
        }
    }
    __syncthreads();

    // ---- inline fp64 band refinement ----
    const int sure = sureCnt;
    const int bc   = min(bandCnt, BANDCAP);
    const int need = TOPK - sure;

    if (bc > need) {   // contested: exact fp64 ranking
        const int wd = t >> 5, lane = t & 31;
        const float* xr = x + (size_t)row * DIN;
        for (int c = wd; c < bc; c += 8) {
            const float* wr = Wenc + (size_t)bidx[c] * DIN;
            double s = 0.0;
            for (int j = lane; j < DIN; j += 32)
                s += (double)xr[j] * (double)wr[j];
#pragma unroll
            for (int o = 16; o; o >>= 1)
                s += __shfl_down_sync(0xffffffffu, s, o);
            if (lane == 0) sc[c] = s;
        }
    }
    __syncthreads();

    if (t == 0) {
        int nsel = 0;
        int sel[BANDCAP];
        if (bc <= need) {
            for (int c = 0; c < bc; c++) sel[nsel++] = c;
        } else {
            bool taken[BANDCAP];
            for (int c = 0; c < bc; c++) taken[c] = false;
            for (int r = 0; r < need; r++) {
                int best = -1;
                for (int c = 0; c < bc; c++) {
                    if (taken[c]) continue;
                    if (best < 0 || sc[c] > sc[best] ||
                        (sc[c] == sc[best] && bidx[c] < bidx[best])) best = c;
                }
                taken[best] = true;
                sel[nsel++] = best;
            }
        }
        for (int a = 0; a < nsel; a++) {
            int c = sel[a];
            g_vals[row * TOPK + sure + a] = bval[c];
            g_idxs[row * TOPK + sure + a] = bidx[c];
            z_sp[(size_t)row * DHID + bidx[c]] = bval[c];
        }
        for (int a = sure + nsel; a < TOPK; a++) {
            g_vals[row * TOPK + a] = 0.f;
            g_idxs[row * TOPK + a] = 0;
        }
        for (int a = 1; a < TOPK; a++) {
            float v = g_vals[row * TOPK + a];
            int   ix = g_idxs[row * TOPK + a];
            int b = a - 1;
            while (b >= 0 && g_idxs[row * TOPK + b] > ix) {
                g_vals[row * TOPK + b + 1] = g_vals[row * TOPK + b];
                g_idxs[row * TOPK + b + 1] = g_idxs[row * TOPK + b];
                b--;
            }
            g_vals[row * TOPK + b + 1] = v;
            g_idxs[row * TOPK + b + 1] = ix;
        }
        int pos = 0;
        for (int a = 0; a < TOPK; a++)
            if (g_vals[row * TOPK + a] > 0.f) pos++;
        atomicAdd(&g_pos, pos);
    }
}

// ---------------- decoder ----------------
__global__ void decoder_kernel(const float* __restrict__ WdecT, float* __restrict__ xhat) {
    __shared__ float sv[TOPK];
    __shared__ int   si[TOPK];
    const int row = blockIdx.x, t = threadIdx.x;
    if (t < TOPK) { sv[t] = g_vals[row * TOPK + t]; si[t] = g_idxs[row * TOPK + t]; }
    __syncthreads();
    const int d = t * 4;
    float x0 = 0.f, x1 = 0.f, x2 = 0.f, x3 = 0.f;
#pragma unroll
    for (int k = 0; k < TOPK; k++) {
        float v = sv[k];
        const float4 w = *(const float4*)(WdecT + (size_t)si[k] * DIN + d);
        x0 += v * w.x; x1 += v * w.y; x2 += v * w.z; x3 += v * w.w;
    }
    *(float4*)(xhat + (size_t)row * DIN + d) = make_float4(x0, x1, x2, x3);
}

// ---------------- active ----------------
__global__ void finalize_kernel(float* __restrict__ act) {
    *act = (float)g_pos / (float)NROWS;
}

// ---------------- launch ----------------
extern "C" void kernel_launch(void* const* d_in, const int* in_sizes, int n_in,
                              void* d_out, int out_size) {
    const float* x     = (const float*)d_in[0];
    const float* W_enc = (const float*)d_in[1];
    const float* W_dec = (const float*)d_in[2];
    float* out = (float*)d_out;

    float* xhat = out + OFF_XHAT;
    float* z_sp = out + OFF_ZSP;
    float* z    = out + OFF_Z;
    float* act  = out + OFF_ACT;

    float* WdecT;
    cudaGetSymbolAddress((void**)&WdecT, g_WdecT);
    unsigned char *xh, *wh;
    cudaGetSymbolAddress((void**)&xh, g_xh);
    cudaGetSymbolAddress((void**)&wh, g_wh);

    cudaFuncSetAttribute(mma_gemm_kernel, cudaFuncAttributeMaxDynamicSharedMemorySize, GEMM_SMEM);

    reset_kernel<<<NROWS / 256, 256>>>();
    packh_kernel<<<(NROWS * DIN / 8 + 255) / 256, 256>>>((const float4*)x, (uint4*)xh, NROWS * DIN / 8);
    packh_kernel<<<(DHID * DIN / 8 + 255) / 256, 256>>>((const float4*)W_enc, (uint4*)wh, DHID * DIN / 8);
    transpose_kernel<<<dim3(DHID / 32, DIN / 32), dim3(32, 8)>>>(W_dec, WdecT);
    mma_gemm_kernel<<<dim3(DHID / 128, NROWS / 128), 256, GEMM_SMEM>>>(xh, wh, z, z_sp);
    select_kernel<<<NROWS, 256>>>(z, x, W_enc, z_sp);
    decoder_kernel<<<NROWS, 256>>>(WdecT, xhat);
    finalize_kernel<<<1, 1>>>(act);
}

// round 11
// speedup vs baseline: 5.6773x; 1.0141x over previous
#include <cuda_runtime.h>
#include <cuda_bf16.h>
#include <cuda_fp16.h>
#include <cstdint>

// Problem constants
#define NROWS   8192
#define DIN     1024
#define DHID    16384
#define TOPK    32
#define BANDCAP 64
#define CAP     1024          // candidate buffer per row
#define TAU     0.78f         // static candidate threshold (~2.3 sigma)
#define BANDM   1e-3f         // refinement band half-width

// Output layout:
//   x_hat    [8192,1024]   @ 0
//   z_sparse [8192,16384]  @ 8388608
//   z        [8192,16384]  @ 142606336
//   active   scalar        @ 276824064
#define OFF_XHAT   0
#define OFF_ZSP    8388608
#define OFF_Z      142606336
#define OFF_ACT    276824064

// -------- device scratch (no allocations allowed) --------
__device__ __half g_WdecT[(size_t)DHID * DIN];                               // 32 MB fp16
__device__ __align__(256) unsigned char g_xh[(size_t)NROWS * DIN * 2];       // fp16 x
__device__ __align__(256) unsigned char g_wh[(size_t)DHID * DIN * 2];        // fp16 W_enc
__device__ uint2 g_cand[(size_t)NROWS * CAP];                                // 64 MB (valbits, idx)
__device__ int   g_cand_cnt[NROWS];
__device__ int   g_pos;

// ---------------- PTX helpers (baseline compute_103 feature set only) -------
__device__ __forceinline__ uint32_t smem_u32(const void* p) {
    uint32_t a;
    asm("{ .reg .u64 t; cvta.to.shared.u64 t, %1; cvt.u32.u64 %0, t; }" : "=r"(a) : "l"(p));
    return a;
}
__device__ __forceinline__ void cp16(uint32_t dst, const void* src) {
    asm volatile("cp.async.cg.shared.global [%0], [%1], 16;" :: "r"(dst), "l"(src));
}
#define CP_COMMIT() asm volatile("cp.async.commit_group;" ::: "memory")
#define CP_WAIT1()  asm volatile("cp.async.wait_group 1;" ::: "memory")

__device__ __forceinline__ void ldm4(uint32_t* d, uint32_t addr) {
    asm volatile("ldmatrix.sync.aligned.m8n8.x4.shared.b16 {%0,%1,%2,%3}, [%4];"
        : "=r"(d[0]), "=r"(d[1]), "=r"(d[2]), "=r"(d[3]) : "r"(addr));
}
__device__ __forceinline__ void mma_f16(float* c, const uint32_t* a, const uint32_t* b) {
    asm volatile("mma.sync.aligned.m16n8k16.row.col.f32.f16.f16.f32 "
        "{%0,%1,%2,%3}, {%4,%5,%6,%7}, {%8,%9}, {%0,%1,%2,%3};"
        : "+f"(c[0]), "+f"(c[1]), "+f"(c[2]), "+f"(c[3])
        : "r"(a[0]), "r"(a[1]), "r"(a[2]), "r"(a[3]), "r"(b[0]), "r"(b[1]));
}

// conflict-free chunk swizzle for 64B rows
__device__ __forceinline__ uint32_t swz(int r, int c16) {
    return (uint32_t)(r * 64 + ((c16 ^ ((r >> 1) & 3)) << 4));
}

// ---------------- reset: g_pos + candidate counters ----------------
__global__ void reset_kernel() {
    int i = blockIdx.x * blockDim.x + threadIdx.x;
    if (i < NROWS) g_cand_cnt[i] = 0;
    if (i == 0) g_pos = 0;
}

// ---------------- pack: fp32 -> fp16, 8 elems/thread -------------------------
__global__ void packh_kernel(const float4* __restrict__ src, uint4* __restrict__ dst, int n8) {
    int i = blockIdx.x * blockDim.x + threadIdx.x;
    if (i >= n8) return;
    float4 a = src[2 * i], b = src[2 * i + 1];
    __half2 h0 = __floats2half2_rn(a.x, a.y);
    __half2 h1 = __floats2half2_rn(a.z, a.w);
    __half2 h2 = __floats2half2_rn(b.x, b.y);
    __half2 h3 = __floats2half2_rn(b.z, b.w);
    uint4 o;
    o.x = *reinterpret_cast<unsigned*>(&h0);
    o.y = *reinterpret_cast<unsigned*>(&h1);
    o.z = *reinterpret_cast<unsigned*>(&h2);
    o.w = *reinterpret_cast<unsigned*>(&h3);
    dst[i] = o;
}

// ---------------- W_dec transpose: [DIN,DHID] fp32 -> [DHID,DIN] fp16 --------
__global__ void transpose_kernel(const float* __restrict__ Wdec, __half* __restrict__ WdecT) {
    __shared__ float tile[32][33];
    int h0 = blockIdx.x * 32;
    int d0 = blockIdx.y * 32;
    int tx = threadIdx.x, ty = threadIdx.y;
#pragma unroll
    for (int j = 0; j < 32; j += 8)
        tile[ty + j][tx] = Wdec[(size_t)(d0 + ty + j) * DHID + h0 + tx];
    __syncthreads();
#pragma unroll
    for (int j = 0; j < 32; j += 8)
        WdecT[(size_t)(h0 + ty + j) * DIN + d0 + tx] = __float2half(tile[tx][ty + j]);
}

// ---------------- encoder: fp16 HMMA GEMM + relu + z_sp zeros + candidates --
#define KTILE   32
#define STAGES  3
#define TILE_B  8192
#define STAGE_B 16384
#define GEMM_SMEM (STAGES * STAGE_B)

__global__ __launch_bounds__(256, 2)
void mma_gemm_kernel(const unsigned char* __restrict__ Ah,
                     const unsigned char* __restrict__ Bh,
                     float* __restrict__ z, float* __restrict__ z_sp) {
    extern __shared__ unsigned char smem[];
    const uint32_t sb = smem_u32(smem);
    const int tid = threadIdx.x;
    const int lane = tid & 31, warp = tid >> 5;
    const int wm = warp & 3, wn = warp >> 2;
    const int m0 = blockIdx.y * 128, n0 = blockIdx.x * 128;

    float acc[2][8][4];
#pragma unroll
    for (int i = 0; i < 2; i++)
#pragma unroll
        for (int j = 0; j < 8; j++)
#pragma unroll
            for (int q = 0; q < 4; q++) acc[i][j][q] = 0.f;

    auto load_stage = [&](int s, int kc) {
        const uint32_t stage = sb + s * STAGE_B;
#pragma unroll
        for (int t = 0; t < 2; t++) {
            const int r0 = t ? n0 : m0;
            const unsigned char* g = t ? Bh : Ah;
#pragma unroll
            for (int rep = 0; rep < 2; rep++) {
                const int j = tid + rep * 256;
                const int r = j >> 2, c16 = j & 3;
                const unsigned char* src = g + (((size_t)(r0 + r) << 10) + kc * 32 + c16 * 8) * 2;
                cp16(stage + t * TILE_B + swz(r, c16), src);
            }
        }
    };

    load_stage(0, 0); CP_COMMIT();
    load_stage(1, 1); CP_COMMIT();

    for (int kc = 0; kc < DIN / KTILE; kc++) {
        CP_WAIT1();                      // stage kc's data complete
        __syncthreads();                 // all threads done reading stage kc-1
        if (kc + 2 < DIN / KTILE) load_stage((kc + 2) % STAGES, kc + 2);
        CP_COMMIT();
        const uint32_t stage = sb + (kc % STAGES) * STAGE_B;

#pragma unroll
        for (int ks = 0; ks < 2; ks++) {
            uint32_t ah[2][4], bh[8][2];
#pragma unroll
            for (int i = 0; i < 2; i++) {
                const int row = wm * 32 + i * 16 + (lane & 15);
                const int c16 = ks * 2 + (lane >> 4);
                ldm4(ah[i], stage + swz(row, c16));
            }
#pragma unroll
            for (int g = 0; g < 4; g++) {
                const int row = wn * 64 + g * 16 + (lane & 7) + ((lane >> 4) << 3);
                const int c16 = ks * 2 + ((lane >> 3) & 1);
                uint32_t d[4];
                ldm4(d, stage + TILE_B + swz(row, c16));
                bh[2 * g][0] = d[0]; bh[2 * g][1] = d[1];
                bh[2 * g + 1][0] = d[2]; bh[2 * g + 1][1] = d[3];
            }
#pragma unroll
            for (int i = 0; i < 2; i++)
#pragma unroll
                for (int j = 0; j < 8; j++)
                    mma_f16(acc[i][j], ah[i], bh[j]);
        }
    }

    // epilogue: relu + z store + z_sp zero store + candidate push (v > TAU)
    const int mbase = m0 + wm * 32, nbase = n0 + wn * 64;
    const float2 zero2 = make_float2(0.f, 0.f);
#pragma unroll
    for (int i = 0; i < 2; i++)
#pragma unroll
        for (int j = 0; j < 8; j++) {
            const int r = mbase + i * 16 + (lane >> 2);
            const int c = nbase + j * 8 + (lane & 3) * 2;
            float2 v0, v1;
            v0.x = fmaxf(acc[i][j][0], 0.f); v0.y = fmaxf(acc[i][j][1], 0.f);
            v1.x = fmaxf(acc[i][j][2], 0.f); v1.y = fmaxf(acc[i][j][3], 0.f);
            *(float2*)(z + (size_t)r * DHID + c) = v0;
            *(float2*)(z + (size_t)(r + 8) * DHID + c) = v1;
            *(float2*)(z_sp + (size_t)r * DHID + c) = zero2;
            *(float2*)(z_sp + (size_t)(r + 8) * DHID + c) = zero2;
            if (v0.x > TAU) { int s = atomicAdd(&g_cand_cnt[r], 1);
                if (s < CAP) g_cand[(size_t)r * CAP + s] = make_uint2(__float_as_uint(v0.x), c); }
            if (v0.y > TAU) { int s = atomicAdd(&g_cand_cnt[r], 1);
                if (s < CAP) g_cand[(size_t)r * CAP + s] = make_uint2(__float_as_uint(v0.y), c + 1); }
            if (v1.x > TAU) { int s = atomicAdd(&g_cand_cnt[r + 8], 1);
                if (s < CAP) g_cand[(size_t)(r + 8) * CAP + s] = make_uint2(__float_as_uint(v1.x), c); }
            if (v1.y > TAU) { int s = atomicAdd(&g_cand_cnt[r + 8], 1);
                if (s < CAP) g_cand[(size_t)(r + 8) * CAP + s] = make_uint2(__float_as_uint(v1.y), c + 1); }
        }
}

// ---------------- merged: top-k + fallback + fp64 refine + DECODER ----------
// One block (256 threads) per row. Selection keeps the 32 winners in smem,
// then the whole block runs the sparse decoder inline (fp16 weights).
__global__ void select_kernel(const float* __restrict__ z,
                              const float* __restrict__ x,
                              const float* __restrict__ Wenc,
                              const __half* __restrict__ WdecT,
                              float* __restrict__ z_sp,
                              float* __restrict__ xhat) {
    __shared__ float cv[CAP];
    __shared__ int   ci[CAP];
    __shared__ int   hist[2048];
    __shared__ float sT;
    __shared__ int sureCnt, bandCnt;
    __shared__ int   bidx[BANDCAP];
    __shared__ float bval[BANDCAP];
    __shared__ double sc[BANDCAP];
    __shared__ float sv_s[TOPK];
    __shared__ int   si_s[TOPK];

    const int row = blockIdx.x, t = threadIdx.x;
    const int cnt = g_cand_cnt[row];
    if (t == 0) { sureCnt = 0; bandCnt = 0; }
    __syncthreads();

    if (cnt >= 48 && cnt <= CAP) {
        // ---- fast path: rank-select over candidates ----
        for (int i = t; i < cnt; i += 256) {
            uint2 p = g_cand[(size_t)row * CAP + i];
            cv[i] = __uint_as_float(p.x);
            ci[i] = (int)p.y;
        }
        __syncthreads();

        // exact rank under strict total order (value desc, index asc)
        for (int c = t; c < cnt; c += 256) {
            float v = cv[c]; int ix = ci[c];
            int rank = 0;
            for (int j = 0; j < cnt; j++) {
                float u = cv[j];
                rank += (u > v) || (u == v && ci[j] < ix);
            }
            if (rank == TOPK - 1) sT = v;
        }
        __syncthreads();

        const float T = sT, hi = T + BANDM, lo = T - BANDM;
        for (int c = t; c < cnt; c += 256) {
            float v = cv[c];
            if (v > hi) {
                int s = atomicAdd(&sureCnt, 1);
                sv_s[s] = v;
                si_s[s] = ci[c];
                z_sp[(size_t)row * DHID + ci[c]] = v;
            } else if (v >= lo) {
                int e = atomicAdd(&bandCnt, 1);
                if (e < BANDCAP) { bidx[e] = ci[c]; bval[e] = v; }
            }
        }
    } else {
        // ---- fallback: dense radix-select over the z row ----
        const float* zr = z + (size_t)row * DHID;
        unsigned prefix = 0;
        int curShift = 32;
        int need = TOPK;
        const int SH[4] = {21, 13, 5, 0};
        __shared__ unsigned s_prefix;
        __shared__ int s_need;

#pragma unroll
        for (int l = 0; l < 4; l++) {
            const int shift = SH[l];
            const int nb = 1 << (curShift - shift);
            for (int i = t; i < nb; i += 256) hist[i] = 0;
            __syncthreads();
            for (int i = t; i < DHID; i += 256) {
                unsigned b = __float_as_uint(zr[i]);
                if (curShift >= 32 || (b >> curShift) == prefix)
                    atomicAdd(&hist[(b >> shift) & (nb - 1)], 1);
            }
            __syncthreads();
            if (t == 0) {
                int nd = need, bb;
                for (bb = nb - 1; bb > 0; bb--) {
                    int c = hist[bb];
                    if (c >= nd) break;
                    nd -= c;
                }
                s_prefix = (prefix << (curShift - shift)) | (unsigned)bb;
                s_need = nd;
            }
            __syncthreads();
            prefix = s_prefix;
            need = s_need;
            curShift = shift;
            __syncthreads();
        }

        const float Tf = __uint_as_float(prefix);
        const float hi = Tf + BANDM, lo = Tf - BANDM;
        for (int i = t; i < DHID; i += 256) {
            float v = zr[i];
            if (v > hi) {
                int s = atomicAdd(&sureCnt, 1);
                sv_s[s] = v;
                si_s[s] = i;
                z_sp[(size_t)row * DHID + i] = v;
            } else if (v >= lo) {
                int e = atomicAdd(&bandCnt, 1);
                if (e < BANDCAP) { bidx[e] = i; bval[e] = v; }
            }
        }
    }
    __syncthreads();

    // ---- inline fp64 band refinement ----
    const int sure = sureCnt;
    const int bc   = min(bandCnt, BANDCAP);
    const int need = TOPK - sure;

    if (bc > need) {   // contested: exact fp64 ranking
        const int wd = t >> 5, lane = t & 31;
        const float* xr = x + (size_t)row * DIN;
        for (int c = wd; c < bc; c += 8) {
            const float* wr = Wenc + (size_t)bidx[c] * DIN;
            double s = 0.0;
            for (int j = lane; j < DIN; j += 32)
                s += (double)xr[j] * (double)wr[j];
#pragma unroll
            for (int o = 16; o; o >>= 1)
                s += __shfl_down_sync(0xffffffffu, s, o);
            if (lane == 0) sc[c] = s;
        }
    }
    __syncthreads();

    if (t == 0) {
        int nsel = 0;
        int sel[BANDCAP];
        if (bc <= need) {
            for (int c = 0; c < bc; c++) sel[nsel++] = c;
        } else {
            bool taken[BANDCAP];
            for (int c = 0; c < bc; c++) taken[c] = false;
            for (int r = 0; r < need; r++) {
                int best = -1;
                for (int c = 0; c < bc; c++) {
                    if (taken[c]) continue;
                    if (best < 0 || sc[c] > sc[best] ||
                        (sc[c] == sc[best] && bidx[c] < bidx[best])) best = c;
                }
                taken[best] = true;
                sel[nsel++] = best;
            }
        }
        for (int a = 0; a < nsel; a++) {
            int c = sel[a];
            sv_s[sure + a] = bval[c];
            si_s[sure + a] = bidx[c];
            z_sp[(size_t)row * DHID + bidx[c]] = bval[c];
        }
        for (int a = sure + nsel; a < TOPK; a++) { sv_s[a] = 0.f; si_s[a] = 0; }
        // sort the 32 by index (smem, serial but tiny)
        for (int a = 1; a < TOPK; a++) {
            float v = sv_s[a]; int ix = si_s[a];
            int b = a - 1;
            while (b >= 0 && si_s[b] > ix) {
                sv_s[b + 1] = sv_s[b]; si_s[b + 1] = si_s[b]; b--;
            }
            sv_s[b + 1] = v; si_s[b + 1] = ix;
        }
        int pos = 0;
        for (int a = 0; a < TOPK; a++)
            if (sv_s[a] > 0.f) pos++;
        atomicAdd(&g_pos, pos);
    }
    __syncthreads();

    // ---- inline decoder: x_hat[row,:] = sum_k sv * WdecT[si,:] (fp16 w) ----
    const int d = t * 4;
    float x0 = 0.f, x1 = 0.f, x2 = 0.f, x3 = 0.f;
#pragma unroll
    for (int k = 0; k < TOPK; k++) {
        const float v = sv_s[k];
        const uint2 w8 = *(const uint2*)(WdecT + (size_t)si_s[k] * DIN + d);
        const __half2 w01 = *reinterpret_cast<const __half2*>(&w8.x);
        const __half2 w23 = *reinterpret_cast<const __half2*>(&w8.y);
        const float2 f01 = __half22float2(w01);
        const float2 f23 = __half22float2(w23);
        x0 += v * f01.x; x1 += v * f01.y; x2 += v * f23.x; x3 += v * f23.y;
    }
    *(float4*)(xhat + (size_t)row * DIN + d) = make_float4(x0, x1, x2, x3);
}

// ---------------- active ----------------
__global__ void finalize_kernel(float* __restrict__ act) {
    *act = (float)g_pos / (float)NROWS;
}

// ---------------- launch ----------------
extern "C" void kernel_launch(void* const* d_in, const int* in_sizes, int n_in,
                              void* d_out, int out_size) {
    const float* x     = (const float*)d_in[0];
    const float* W_enc = (const float*)d_in[1];
    const float* W_dec = (const float*)d_in[2];
    float* out = (float*)d_out;

    float* xhat = out + OFF_XHAT;
    float* z_sp = out + OFF_ZSP;
    float* z    = out + OFF_Z;
    float* act  = out + OFF_ACT;

    __half* WdecT;
    cudaGetSymbolAddress((void**)&WdecT, g_WdecT);
    unsigned char *xh, *wh;
    cudaGetSymbolAddress((void**)&xh, g_xh);
    cudaGetSymbolAddress((void**)&wh, g_wh);

    cudaFuncSetAttribute(mma_gemm_kernel, cudaFuncAttributeMaxDynamicSharedMemorySize, GEMM_SMEM);

    reset_kernel<<<NROWS / 256, 256>>>();
    packh_kernel<<<(NROWS * DIN / 8 + 255) / 256, 256>>>((const float4*)x, (uint4*)xh, NROWS * DIN / 8);
    packh_kernel<<<(DHID * DIN / 8 + 255) / 256, 256>>>((const float4*)W_enc, (uint4*)wh, DHID * DIN / 8);
    transpose_kernel<<<dim3(DHID / 32, DIN / 32), dim3(32, 8)>>>(W_dec, WdecT);
    mma_gemm_kernel<<<dim3(DHID / 128, NROWS / 128), 256, GEMM_SMEM>>>(xh, wh, z, z_sp);
    select_kernel<<<NROWS, 256>>>(z, x, W_enc, WdecT, z_sp, xhat);
    finalize_kernel<<<1, 1>>>(act);
}

// round 12
// speedup vs baseline: 5.8656x; 1.0332x over previous
#include <cuda_runtime.h>
#include <cuda_bf16.h>
#include <cuda_fp16.h>
#include <cstdint>

// Problem constants
#define NROWS   8192
#define DIN     1024
#define DHID    16384
#define TOPK    32
#define BANDCAP 64
#define CAP     1024          // candidate buffer per row
#define TAU     0.78f         // static candidate threshold (~2.3 sigma)
#define BANDM   1e-3f         // refinement band half-width

// Output layout:
//   x_hat    [8192,1024]   @ 0
//   z_sparse [8192,16384]  @ 8388608
//   z        [8192,16384]  @ 142606336
//   active   scalar        @ 276824064
#define OFF_XHAT   0
#define OFF_ZSP    8388608
#define OFF_Z      142606336
#define OFF_ACT    276824064

// -------- device scratch (no allocations allowed) --------
__device__ __half g_WdecT[(size_t)DHID * DIN];                               // 32 MB fp16
__device__ __align__(256) unsigned char g_xh[(size_t)NROWS * DIN * 2];       // fp16 x
__device__ __align__(256) unsigned char g_wh[(size_t)DHID * DIN * 2];        // fp16 W_enc
__device__ uint2 g_cand[(size_t)NROWS * CAP];                                // 64 MB (valbits, idx)
__device__ int   g_cand_cnt[NROWS];
__device__ int   g_pos;
__device__ int   g_done;

// ---------------- PTX helpers (baseline compute_103 feature set only) -------
__device__ __forceinline__ uint32_t smem_u32(const void* p) {
    uint32_t a;
    asm("{ .reg .u64 t; cvta.to.shared.u64 t, %1; cvt.u32.u64 %0, t; }" : "=r"(a) : "l"(p));
    return a;
}
__device__ __forceinline__ void cp16(uint32_t dst, const void* src) {
    asm volatile("cp.async.cg.shared.global [%0], [%1], 16;" :: "r"(dst), "l"(src));
}
#define CP_COMMIT() asm volatile("cp.async.commit_group;" ::: "memory")
#define CP_WAIT1()  asm volatile("cp.async.wait_group 1;" ::: "memory")

__device__ __forceinline__ void ldm4(uint32_t* d, uint32_t addr) {
    asm volatile("ldmatrix.sync.aligned.m8n8.x4.shared.b16 {%0,%1,%2,%3}, [%4];"
        : "=r"(d[0]), "=r"(d[1]), "=r"(d[2]), "=r"(d[3]) : "r"(addr));
}
__device__ __forceinline__ void mma_f16(float* c, const uint32_t* a, const uint32_t* b) {
    asm volatile("mma.sync.aligned.m16n8k16.row.col.f32.f16.f16.f32 "
        "{%0,%1,%2,%3}, {%4,%5,%6,%7}, {%8,%9}, {%0,%1,%2,%3};"
        : "+f"(c[0]), "+f"(c[1]), "+f"(c[2]), "+f"(c[3])
        : "r"(a[0]), "r"(a[1]), "r"(a[2]), "r"(a[3]), "r"(b[0]), "r"(b[1]));
}

// conflict-free chunk swizzle for 64B rows
__device__ __forceinline__ uint32_t swz(int r, int c16) {
    return (uint32_t)(r * 64 + ((c16 ^ ((r >> 1) & 3)) << 4));
}

// ---------------- merged prep: transpose + pack W + pack x + reset ----------
// block ranges:
//   [0, 16384)       W_dec transpose -> fp16 WdecT
//   [16384, 24576)   pack W_enc -> fp16      (8192 blocks, 2048 elems each)
//   [24576, 28672)   pack x -> fp16          (4096 blocks)
//   [28672, 28704)   reset counters          (32 blocks)
__global__ void prep_kernel(const float* __restrict__ x,
                            const float* __restrict__ Wenc,
                            const float* __restrict__ Wdec,
                            __half* __restrict__ WdecT,
                            uint4* __restrict__ xh, uint4* __restrict__ wh) {
    const int b = blockIdx.x, t = threadIdx.x;
    if (b < 16384) {
        __shared__ float tile[32][33];
        const int h0 = (b & 511) * 32;
        const int d0 = (b >> 9) * 32;
        const int tx = t & 31, ty = t >> 5;
#pragma unroll
        for (int j = 0; j < 32; j += 8)
            tile[ty + j][tx] = Wdec[(size_t)(d0 + ty + j) * DHID + h0 + tx];
        __syncthreads();
#pragma unroll
        for (int j = 0; j < 32; j += 8)
            WdecT[(size_t)(h0 + ty + j) * DIN + d0 + tx] = __float2half(tile[tx][ty + j]);
    } else if (b < 28672) {
        const bool isW = (b < 24576);
        const int i = (isW ? (b - 16384) : (b - 24576)) * 256 + t;
        const float4* src = (const float4*)(isW ? Wenc : x);
        uint4* dst = isW ? wh : xh;
        float4 a = src[2 * i], c = src[2 * i + 1];
        __half2 h0 = __floats2half2_rn(a.x, a.y);
        __half2 h1 = __floats2half2_rn(a.z, a.w);
        __half2 h2 = __floats2half2_rn(c.x, c.y);
        __half2 h3 = __floats2half2_rn(c.z, c.w);
        uint4 o;
        o.x = *reinterpret_cast<unsigned*>(&h0);
        o.y = *reinterpret_cast<unsigned*>(&h1);
        o.z = *reinterpret_cast<unsigned*>(&h2);
        o.w = *reinterpret_cast<unsigned*>(&h3);
        dst[i] = o;
    } else {
        const int i = (b - 28672) * 256 + t;
        if (i < NROWS) g_cand_cnt[i] = 0;
        if (i == 0) { g_pos = 0; g_done = 0; }
    }
}

// ---------------- encoder: fp16 HMMA GEMM + relu + z_sp zeros + candidates --
#define KTILE   32
#define STAGES  3
#define TILE_B  8192
#define STAGE_B 16384
#define GEMM_SMEM (STAGES * STAGE_B)

__global__ __launch_bounds__(256, 2)
void mma_gemm_kernel(const unsigned char* __restrict__ Ah,
                     const unsigned char* __restrict__ Bh,
                     float* __restrict__ z, float* __restrict__ z_sp) {
    extern __shared__ unsigned char smem[];
    const uint32_t sb = smem_u32(smem);
    const int tid = threadIdx.x;
    const int lane = tid & 31, warp = tid >> 5;
    const int wm = warp & 3, wn = warp >> 2;
    const int m0 = blockIdx.y * 128, n0 = blockIdx.x * 128;

    float acc[2][8][4];
#pragma unroll
    for (int i = 0; i < 2; i++)
#pragma unroll
        for (int j = 0; j < 8; j++)
#pragma unroll
            for (int q = 0; q < 4; q++) acc[i][j][q] = 0.f;

    auto load_stage = [&](int s, int kc) {
        const uint32_t stage = sb + s * STAGE_B;
#pragma unroll
        for (int t = 0; t < 2; t++) {
            const int r0 = t ? n0 : m0;
            const unsigned char* g = t ? Bh : Ah;
#pragma unroll
            for (int rep = 0; rep < 2; rep++) {
                const int j = tid + rep * 256;
                const int r = j >> 2, c16 = j & 3;
                const unsigned char* src = g + (((size_t)(r0 + r) << 10) + kc * 32 + c16 * 8) * 2;
                cp16(stage + t * TILE_B + swz(r, c16), src);
            }
        }
    };

    load_stage(0, 0); CP_COMMIT();
    load_stage(1, 1); CP_COMMIT();

    for (int kc = 0; kc < DIN / KTILE; kc++) {
        CP_WAIT1();                      // stage kc's data complete
        __syncthreads();                 // all threads done reading stage kc-1
        if (kc + 2 < DIN / KTILE) load_stage((kc + 2) % STAGES, kc + 2);
        CP_COMMIT();
        const uint32_t stage = sb + (kc % STAGES) * STAGE_B;

#pragma unroll
        for (int ks = 0; ks < 2; ks++) {
            uint32_t ah[2][4], bh[8][2];
#pragma unroll
            for (int i = 0; i < 2; i++) {
                const int row = wm * 32 + i * 16 + (lane & 15);
                const int c16 = ks * 2 + (lane >> 4);
                ldm4(ah[i], stage + swz(row, c16));
            }
#pragma unroll
            for (int g = 0; g < 4; g++) {
                const int row = wn * 64 + g * 16 + (lane & 7) + ((lane >> 4) << 3);
                const int c16 = ks * 2 + ((lane >> 3) & 1);
                uint32_t d[4];
                ldm4(d, stage + TILE_B + swz(row, c16));
                bh[2 * g][0] = d[0]; bh[2 * g][1] = d[1];
                bh[2 * g + 1][0] = d[2]; bh[2 * g + 1][1] = d[3];
            }
#pragma unroll
            for (int i = 0; i < 2; i++)
#pragma unroll
                for (int j = 0; j < 8; j++)
                    mma_f16(acc[i][j], ah[i], bh[j]);
        }
    }

    // epilogue: relu + z store + z_sp zero store + candidate push (v > TAU)
    const int mbase = m0 + wm * 32, nbase = n0 + wn * 64;
    const float2 zero2 = make_float2(0.f, 0.f);
#pragma unroll
    for (int i = 0; i < 2; i++)
#pragma unroll
        for (int j = 0; j < 8; j++) {
            const int r = mbase + i * 16 + (lane >> 2);
            const int c = nbase + j * 8 + (lane & 3) * 2;
            float2 v0, v1;
            v0.x = fmaxf(acc[i][j][0], 0.f); v0.y = fmaxf(acc[i][j][1], 0.f);
            v1.x = fmaxf(acc[i][j][2], 0.f); v1.y = fmaxf(acc[i][j][3], 0.f);
            *(float2*)(z + (size_t)r * DHID + c) = v0;
            *(float2*)(z + (size_t)(r + 8) * DHID + c) = v1;
            *(float2*)(z_sp + (size_t)r * DHID + c) = zero2;
            *(float2*)(z_sp + (size_t)(r + 8) * DHID + c) = zero2;
            if (v0.x > TAU) { int s = atomicAdd(&g_cand_cnt[r], 1);
                if (s < CAP) g_cand[(size_t)r * CAP + s] = make_uint2(__float_as_uint(v0.x), c); }
            if (v0.y > TAU) { int s = atomicAdd(&g_cand_cnt[r], 1);
                if (s < CAP) g_cand[(size_t)r * CAP + s] = make_uint2(__float_as_uint(v0.y), c + 1); }
            if (v1.x > TAU) { int s = atomicAdd(&g_cand_cnt[r + 8], 1);
                if (s < CAP) g_cand[(size_t)(r + 8) * CAP + s] = make_uint2(__float_as_uint(v1.x), c); }
            if (v1.y > TAU) { int s = atomicAdd(&g_cand_cnt[r + 8], 1);
                if (s < CAP) g_cand[(size_t)(r + 8) * CAP + s] = make_uint2(__float_as_uint(v1.y), c + 1); }
        }
}

// ---------------- merged: top-k + fallback + fp64 refine + decoder + active -
// One block (256 threads) per row; the last block to finish writes `active`.
__global__ void select_kernel(const float* __restrict__ z,
                              const float* __restrict__ x,
                              const float* __restrict__ Wenc,
                              const __half* __restrict__ WdecT,
                              float* __restrict__ z_sp,
                              float* __restrict__ xhat,
                              float* __restrict__ act) {
    __shared__ float cv[CAP];
    __shared__ int   ci[CAP];
    __shared__ int   hist[2048];
    __shared__ float xs[DIN];
    __shared__ float sT;
    __shared__ int sureCnt, bandCnt;
    __shared__ int   bidx[BANDCAP];
    __shared__ float bval[BANDCAP];
    __shared__ double sc[BANDCAP];
    __shared__ float sv_s[TOPK];
    __shared__ int   si_s[TOPK];

    const int row = blockIdx.x, t = threadIdx.x;
    const int cnt = g_cand_cnt[row];
    if (t == 0) { sureCnt = 0; bandCnt = 0; }
    __syncthreads();

    if (cnt >= 48 && cnt <= CAP) {
        // ---- fast path: rank-select over candidates ----
        for (int i = t; i < cnt; i += 256) {
            uint2 p = g_cand[(size_t)row * CAP + i];
            cv[i] = __uint_as_float(p.x);
            ci[i] = (int)p.y;
        }
        __syncthreads();

        // exact rank under strict total order (value desc, index asc)
        for (int c = t; c < cnt; c += 256) {
            float v = cv[c]; int ix = ci[c];
            int rank = 0;
            for (int j = 0; j < cnt; j++) {
                float u = cv[j];
                rank += (u > v) || (u == v && ci[j] < ix);
            }
            if (rank == TOPK - 1) sT = v;
        }
        __syncthreads();

        const float T = sT, hi = T + BANDM, lo = T - BANDM;
        for (int c = t; c < cnt; c += 256) {
            float v = cv[c];
            if (v > hi) {
                int s = atomicAdd(&sureCnt, 1);
                sv_s[s] = v;
                si_s[s] = ci[c];
                z_sp[(size_t)row * DHID + ci[c]] = v;
            } else if (v >= lo) {
                int e = atomicAdd(&bandCnt, 1);
                if (e < BANDCAP) { bidx[e] = ci[c]; bval[e] = v; }
            }
        }
    } else {
        // ---- fallback: dense radix-select over the z row ----
        const float* zr = z + (size_t)row * DHID;
        unsigned prefix = 0;
        int curShift = 32;
        int need = TOPK;
        const int SH[4] = {21, 13, 5, 0};
        __shared__ unsigned s_prefix;
        __shared__ int s_need;

#pragma unroll
        for (int l = 0; l < 4; l++) {
            const int shift = SH[l];
            const int nb = 1 << (curShift - shift);
            for (int i = t; i < nb; i += 256) hist[i] = 0;
            __syncthreads();
            for (int i = t; i < DHID; i += 256) {
                unsigned b = __float_as_uint(zr[i]);
                if (curShift >= 32 || (b >> curShift) == prefix)
                    atomicAdd(&hist[(b >> shift) & (nb - 1)], 1);
            }
            __syncthreads();
            if (t == 0) {
                int nd = need, bb;
                for (bb = nb - 1; bb > 0; bb--) {
                    int c = hist[bb];
                    if (c >= nd) break;
                    nd -= c;
                }
                s_prefix = (prefix << (curShift - shift)) | (unsigned)bb;
                s_need = nd;
            }
            __syncthreads();
            prefix = s_prefix;
            need = s_need;
            curShift = shift;
            __syncthreads();
        }

        const float Tf = __uint_as_float(prefix);
        const float hi = Tf + BANDM, lo = Tf - BANDM;
        for (int i = t; i < DHID; i += 256) {
            float v = zr[i];
            if (v > hi) {
                int s = atomicAdd(&sureCnt, 1);
                sv_s[s] = v;
                si_s[s] = i;
                z_sp[(size_t)row * DHID + i] = v;
            } else if (v >= lo) {
                int e = atomicAdd(&bandCnt, 1);
                if (e < BANDCAP) { bidx[e] = i; bval[e] = v; }
            }
        }
    }
    __syncthreads();

    // ---- inline fp64 band refinement ----
    const int sure = sureCnt;
    const int bc   = min(bandCnt, BANDCAP);
    const int need = TOPK - sure;

    if (bc > need) {   // contested: exact fp64 ranking
        // cache x row in smem once (each candidate re-reads it 32x otherwise)
        for (int j = t; j < DIN; j += 256) xs[j] = x[(size_t)row * DIN + j];
        __syncthreads();
        const int wd = t >> 5, lane = t & 31;
        for (int c = wd; c < bc; c += 8) {
            const float* wr = Wenc + (size_t)bidx[c] * DIN;
            double s = 0.0;
            for (int j = lane; j < DIN; j += 32)
                s += (double)xs[j] * (double)wr[j];
#pragma unroll
            for (int o = 16; o; o >>= 1)
                s += __shfl_down_sync(0xffffffffu, s, o);
            if (lane == 0) sc[c] = s;
        }
    }
    __syncthreads();

    if (t == 0) {
        int nsel = 0;
        int sel[BANDCAP];
        if (bc <= need) {
            for (int c = 0; c < bc; c++) sel[nsel++] = c;
        } else {
            bool taken[BANDCAP];
            for (int c = 0; c < bc; c++) taken[c] = false;
            for (int r = 0; r < need; r++) {
                int best = -1;
                for (int c = 0; c < bc; c++) {
                    if (taken[c]) continue;
                    if (best < 0 || sc[c] > sc[best] ||
                        (sc[c] == sc[best] && bidx[c] < bidx[best])) best = c;
                }
                taken[best] = true;
                sel[nsel++] = best;
            }
        }
        for (int a = 0; a < nsel; a++) {
            int c = sel[a];
            sv_s[sure + a] = bval[c];
            si_s[sure + a] = bidx[c];
            z_sp[(size_t)row * DHID + bidx[c]] = bval[c];
        }
        for (int a = sure + nsel; a < TOPK; a++) { sv_s[a] = 0.f; si_s[a] = 0; }
        // sort the 32 by index (smem, serial but tiny)
        for (int a = 1; a < TOPK; a++) {
            float v = sv_s[a]; int ix = si_s[a];
            int b = a - 1;
            while (b >= 0 && si_s[b] > ix) {
                sv_s[b + 1] = sv_s[b]; si_s[b + 1] = si_s[b]; b--;
            }
            sv_s[b + 1] = v; si_s[b + 1] = ix;
        }
        int pos = 0;
        for (int a = 0; a < TOPK; a++)
            if (sv_s[a] > 0.f) pos++;
        atomicAdd(&g_pos, pos);
    }
    __syncthreads();

    // ---- inline decoder: x_hat[row,:] = sum_k sv * WdecT[si,:] (fp16 w) ----
    const int d = t * 4;
    float x0 = 0.f, x1 = 0.f, x2 = 0.f, x3 = 0.f;
#pragma unroll
    for (int k = 0; k < TOPK; k++) {
        const float v = sv_s[k];
        const uint2 w8 = *(const uint2*)(WdecT + (size_t)si_s[k] * DIN + d);
        const __half2 w01 = *reinterpret_cast<const __half2*>(&w8.x);
        const __half2 w23 = *reinterpret_cast<const __half2*>(&w8.y);
        const float2 f01 = __half22float2(w01);
        const float2 f23 = __half22float2(w23);
        x0 += v * f01.x; x1 += v * f01.y; x2 += v * f23.x; x3 += v * f23.y;
    }
    *(float4*)(xhat + (size_t)row * DIN + d) = make_float4(x0, x1, x2, x3);

    // ---- last block writes `active` ----
    if (t == 0) {
        __threadfence();
        int done = atomicAdd(&g_done, 1);
        if (done == NROWS - 1) {
            int total = atomicAdd(&g_pos, 0);
            *act = (float)total / (float)NROWS;
        }
    }
}

// ---------------- launch ----------------
extern "C" void kernel_launch(void* const* d_in, const int* in_sizes, int n_in,
                              void* d_out, int out_size) {
    const float* x     = (const float*)d_in[0];
    const float* W_enc = (const float*)d_in[1];
    const float* W_dec = (const float*)d_in[2];
    float* out = (float*)d_out;

    float* xhat = out + OFF_XHAT;
    float* z_sp = out + OFF_ZSP;
    float* z    = out + OFF_Z;
    float* act  = out + OFF_ACT;

    __half* WdecT;
    cudaGetSymbolAddress((void**)&WdecT, g_WdecT);
    unsigned char *xh, *wh;
    cudaGetSymbolAddress((void**)&xh, g_xh);
    cudaGetSymbolAddress((void**)&wh, g_wh);

    cudaFuncSetAttribute(mma_gemm_kernel, cudaFuncAttributeMaxDynamicSharedMemorySize, GEMM_SMEM);

    prep_kernel<<<28704, 256>>>(x, W_enc, W_dec, WdecT, (uint4*)xh, (uint4*)wh);
    mma_gemm_kernel<<<dim3(DHID / 128, NROWS / 128), 256, GEMM_SMEM>>>(xh, wh, z, z_sp);
    select_kernel<<<NROWS, 256>>>(z, x, W_enc, WdecT, z_sp, xhat, act);
}

// round 13
// speedup vs baseline: 5.9707x; 1.0179x over previous
#include <cuda_runtime.h>
#include <cuda_bf16.h>
#include <cuda_fp16.h>
#include <cstdint>

// Problem constants
#define NROWS   8192
#define DIN     1024
#define DHID    16384
#define TOPK    32
#define BANDCAP 64
#define CAP     1024          // candidate buffer per row
#define TAU     0.78f         // static candidate threshold (~2.3 sigma)
#define BANDM   1e-3f         // refinement band half-width

// Output layout:
//   x_hat    [8192,1024]   @ 0
//   z_sparse [8192,16384]  @ 8388608
//   z        [8192,16384]  @ 142606336
//   active   scalar        @ 276824064
#define OFF_XHAT   0
#define OFF_ZSP    8388608
#define OFF_Z      142606336
#define OFF_ACT    276824064

// -------- device scratch (no allocations allowed) --------
__device__ __half g_WdecT[(size_t)DHID * DIN];                               // 32 MB fp16
__device__ __align__(256) unsigned char g_xh[(size_t)NROWS * DIN * 2];       // fp16 x
__device__ __align__(256) unsigned char g_wh[(size_t)DHID * DIN * 2];        // fp16 W_enc
__device__ uint2 g_cand[(size_t)NROWS * CAP];                                // 64 MB (valbits, idx)
__device__ int   g_cand_cnt[NROWS];
__device__ int   g_pos;
__device__ int   g_done;

// ---------------- PTX helpers (baseline compute_103 feature set only) -------
__device__ __forceinline__ uint32_t smem_u32(const void* p) {
    uint32_t a;
    asm("{ .reg .u64 t; cvta.to.shared.u64 t, %1; cvt.u32.u64 %0, t; }" : "=r"(a) : "l"(p));
    return a;
}
__device__ __forceinline__ void cp16(uint32_t dst, const void* src) {
    asm volatile("cp.async.cg.shared.global [%0], [%1], 16;" :: "r"(dst), "l"(src));
}
#define CP_COMMIT() asm volatile("cp.async.commit_group;" ::: "memory")
#define CP_WAIT1()  asm volatile("cp.async.wait_group 1;" ::: "memory")

__device__ __forceinline__ void ldm4(uint32_t* d, uint32_t addr) {
    asm volatile("ldmatrix.sync.aligned.m8n8.x4.shared.b16 {%0,%1,%2,%3}, [%4];"
        : "=r"(d[0]), "=r"(d[1]), "=r"(d[2]), "=r"(d[3]) : "r"(addr));
}
__device__ __forceinline__ void mma_f16(float* c, const uint32_t* a, const uint32_t* b) {
    asm volatile("mma.sync.aligned.m16n8k16.row.col.f32.f16.f16.f32 "
        "{%0,%1,%2,%3}, {%4,%5,%6,%7}, {%8,%9}, {%0,%1,%2,%3};"
        : "+f"(c[0]), "+f"(c[1]), "+f"(c[2]), "+f"(c[3])
        : "r"(a[0]), "r"(a[1]), "r"(a[2]), "r"(a[3]), "r"(b[0]), "r"(b[1]));
}

// conflict-free chunk swizzle for 64B rows
__device__ __forceinline__ uint32_t swz(int r, int c16) {
    return (uint32_t)(r * 64 + ((c16 ^ ((r >> 1) & 3)) << 4));
}

// ---------------- prep: pack W_enc + pack x + reset (transpose moved into GEMM)
// block ranges:
//   [0, 8192)        pack W_enc -> fp16      (2048 elems each)
//   [8192, 12288)    pack x -> fp16          (4096 blocks)
//   [12288, 12320)   reset counters          (32 blocks)
__global__ void prep_kernel(const float* __restrict__ x,
                            const float* __restrict__ Wenc,
                            uint4* __restrict__ xh, uint4* __restrict__ wh) {
    const int b = blockIdx.x, t = threadIdx.x;
    if (b < 12288) {
        const bool isW = (b < 8192);
        const int i = (isW ? b : (b - 8192)) * 256 + t;
        const float4* src = (const float4*)(isW ? Wenc : x);
        uint4* dst = isW ? wh : xh;
        float4 a = src[2 * i], c = src[2 * i + 1];
        __half2 h0 = __floats2half2_rn(a.x, a.y);
        __half2 h1 = __floats2half2_rn(a.z, a.w);
        __half2 h2 = __floats2half2_rn(c.x, c.y);
        __half2 h3 = __floats2half2_rn(c.z, c.w);
        uint4 o;
        o.x = *reinterpret_cast<unsigned*>(&h0);
        o.y = *reinterpret_cast<unsigned*>(&h1);
        o.z = *reinterpret_cast<unsigned*>(&h2);
        o.w = *reinterpret_cast<unsigned*>(&h3);
        dst[i] = o;
    } else {
        const int i = (b - 12288) * 256 + t;
        if (i < NROWS) g_cand_cnt[i] = 0;
        if (i == 0) { g_pos = 0; g_done = 0; }
    }
}

// ---------------- encoder: fp16 HMMA GEMM + relu + z_sp zeros + candidates --
// Prologue: each CTA transposes 2 of the 16384 W_dec 32x32 tiles into fp16
// WdecT, reusing the (not yet live) stage smem as scratch — the traffic rides
// the GEMM's idle DRAM; completion before select is implied by kernel order.
#define KTILE   32
#define STAGES  3
#define TILE_B  8192
#define STAGE_B 16384
#define GEMM_SMEM (STAGES * STAGE_B)

__global__ __launch_bounds__(256, 2)
void mma_gemm_kernel(const unsigned char* __restrict__ Ah,
                     const unsigned char* __restrict__ Bh,
                     const float* __restrict__ Wdec,
                     __half* __restrict__ WdecT,
                     float* __restrict__ z, float* __restrict__ z_sp) {
    extern __shared__ unsigned char smem[];
    const uint32_t sb = smem_u32(smem);
    const int tid = threadIdx.x;
    const int lane = tid & 31, warp = tid >> 5;
    const int wm = warp & 3, wn = warp >> 2;
    const int m0 = blockIdx.y * 128, n0 = blockIdx.x * 128;

    // ---- prologue: transpose 2 W_dec tiles using stage smem as scratch ----
    {
        float (*tile)[33] = reinterpret_cast<float (*)[33]>(smem);
        const int L = blockIdx.y * gridDim.x + blockIdx.x;   // 0..8191
        const int tx = tid & 31, ty = tid >> 5;              // (32, 8)
#pragma unroll
        for (int q = 0; q < 2; q++) {
            const int tt = 2 * L + q;
            const int h0 = (tt & 511) * 32;
            const int d0 = (tt >> 9) * 32;
#pragma unroll
            for (int j = 0; j < 32; j += 8)
                tile[ty + j][tx] = Wdec[(size_t)(d0 + ty + j) * DHID + h0 + tx];
            __syncthreads();
#pragma unroll
            for (int j = 0; j < 32; j += 8)
                WdecT[(size_t)(h0 + ty + j) * DIN + d0 + tx] = __float2half(tile[tx][ty + j]);
            __syncthreads();
        }
    }

    float acc[2][8][4];
#pragma unroll
    for (int i = 0; i < 2; i++)
#pragma unroll
        for (int j = 0; j < 8; j++)
#pragma unroll
            for (int q = 0; q < 4; q++) acc[i][j][q] = 0.f;

    auto load_stage = [&](int s, int kc) {
        const uint32_t stage = sb + s * STAGE_B;
#pragma unroll
        for (int t = 0; t < 2; t++) {
            const int r0 = t ? n0 : m0;
            const unsigned char* g = t ? Bh : Ah;
#pragma unroll
            for (int rep = 0; rep < 2; rep++) {
                const int j = tid + rep * 256;
                const int r = j >> 2, c16 = j & 3;
                const unsigned char* src = g + (((size_t)(r0 + r) << 10) + kc * 32 + c16 * 8) * 2;
                cp16(stage + t * TILE_B + swz(r, c16), src);
            }
        }
    };

    load_stage(0, 0); CP_COMMIT();
    load_stage(1, 1); CP_COMMIT();

    for (int kc = 0; kc < DIN / KTILE; kc++) {
        CP_WAIT1();                      // stage kc's data complete
        __syncthreads();                 // all threads done reading stage kc-1
        if (kc + 2 < DIN / KTILE) load_stage((kc + 2) % STAGES, kc + 2);
        CP_COMMIT();
        const uint32_t stage = sb + (kc % STAGES) * STAGE_B;

#pragma unroll
        for (int ks = 0; ks < 2; ks++) {
            uint32_t ah[2][4], bh[8][2];
#pragma unroll
            for (int i = 0; i < 2; i++) {
                const int row = wm * 32 + i * 16 + (lane & 15);
                const int c16 = ks * 2 + (lane >> 4);
                ldm4(ah[i], stage + swz(row, c16));
            }
#pragma unroll
            for (int g = 0; g < 4; g++) {
                const int row = wn * 64 + g * 16 + (lane & 7) + ((lane >> 4) << 3);
                const int c16 = ks * 2 + ((lane >> 3) & 1);
                uint32_t d[4];
                ldm4(d, stage + TILE_B + swz(row, c16));
                bh[2 * g][0] = d[0]; bh[2 * g][1] = d[1];
                bh[2 * g + 1][0] = d[2]; bh[2 * g + 1][1] = d[3];
            }
#pragma unroll
            for (int i = 0; i < 2; i++)
#pragma unroll
                for (int j = 0; j < 8; j++)
                    mma_f16(acc[i][j], ah[i], bh[j]);
        }
    }

    // epilogue: relu + z store + z_sp zero store + candidate push (v > TAU)
    const int mbase = m0 + wm * 32, nbase = n0 + wn * 64;
    const float2 zero2 = make_float2(0.f, 0.f);
#pragma unroll
    for (int i = 0; i < 2; i++)
#pragma unroll
        for (int j = 0; j < 8; j++) {
            const int r = mbase + i * 16 + (lane >> 2);
            const int c = nbase + j * 8 + (lane & 3) * 2;
            float2 v0, v1;
            v0.x = fmaxf(acc[i][j][0], 0.f); v0.y = fmaxf(acc[i][j][1], 0.f);
            v1.x = fmaxf(acc[i][j][2], 0.f); v1.y = fmaxf(acc[i][j][3], 0.f);
            *(float2*)(z + (size_t)r * DHID + c) = v0;
            *(float2*)(z + (size_t)(r + 8) * DHID + c) = v1;
            *(float2*)(z_sp + (size_t)r * DHID + c) = zero2;
            *(float2*)(z_sp + (size_t)(r + 8) * DHID + c) = zero2;
            if (v0.x > TAU) { int s = atomicAdd(&g_cand_cnt[r], 1);
                if (s < CAP) g_cand[(size_t)r * CAP + s] = make_uint2(__float_as_uint(v0.x), c); }
            if (v0.y > TAU) { int s = atomicAdd(&g_cand_cnt[r], 1);
                if (s < CAP) g_cand[(size_t)r * CAP + s] = make_uint2(__float_as_uint(v0.y), c + 1); }
            if (v1.x > TAU) { int s = atomicAdd(&g_cand_cnt[r + 8], 1);
                if (s < CAP) g_cand[(size_t)(r + 8) * CAP + s] = make_uint2(__float_as_uint(v1.x), c); }
            if (v1.y > TAU) { int s = atomicAdd(&g_cand_cnt[r + 8], 1);
                if (s < CAP) g_cand[(size_t)(r + 8) * CAP + s] = make_uint2(__float_as_uint(v1.y), c + 1); }
        }
}

// ---------------- merged: top-k + fallback + fp64 refine + decoder + active -
// One block (256 threads) per row; the last block to finish writes `active`.
__global__ void select_kernel(const float* __restrict__ z,
                              const float* __restrict__ x,
                              const float* __restrict__ Wenc,
                              const __half* __restrict__ WdecT,
                              float* __restrict__ z_sp,
                              float* __restrict__ xhat,
                              float* __restrict__ act) {
    __shared__ float cv[CAP];
    __shared__ int   ci[CAP];
    __shared__ int   hist[2048];
    __shared__ float xs[DIN];
    __shared__ float sT;
    __shared__ int sureCnt, bandCnt;
    __shared__ int   bidx[BANDCAP];
    __shared__ float bval[BANDCAP];
    __shared__ double sc[BANDCAP];
    __shared__ float sv_s[TOPK];
    __shared__ int   si_s[TOPK];

    const int row = blockIdx.x, t = threadIdx.x;
    const int cnt = g_cand_cnt[row];
    if (t == 0) { sureCnt = 0; bandCnt = 0; }
    __syncthreads();

    if (cnt >= 48 && cnt <= CAP) {
        // ---- fast path: rank-select over candidates ----
        for (int i = t; i < cnt; i += 256) {
            uint2 p = g_cand[(size_t)row * CAP + i];
            cv[i] = __uint_as_float(p.x);
            ci[i] = (int)p.y;
        }
        __syncthreads();

        // exact rank under strict total order (value desc, index asc)
        for (int c = t; c < cnt; c += 256) {
            float v = cv[c]; int ix = ci[c];
            int rank = 0;
            for (int j = 0; j < cnt; j++) {
                float u = cv[j];
                rank += (u > v) || (u == v && ci[j] < ix);
            }
            if (rank == TOPK - 1) sT = v;
        }
        __syncthreads();

        const float T = sT, hi = T + BANDM, lo = T - BANDM;
        for (int c = t; c < cnt; c += 256) {
            float v = cv[c];
            if (v > hi) {
                int s = atomicAdd(&sureCnt, 1);
                sv_s[s] = v;
                si_s[s] = ci[c];
                z_sp[(size_t)row * DHID + ci[c]] = v;
            } else if (v >= lo) {
                int e = atomicAdd(&bandCnt, 1);
                if (e < BANDCAP) { bidx[e] = ci[c]; bval[e] = v; }
            }
        }
    } else {
        // ---- fallback: dense radix-select over the z row ----
        const float* zr = z + (size_t)row * DHID;
        unsigned prefix = 0;
        int curShift = 32;
        int need = TOPK;
        const int SH[4] = {21, 13, 5, 0};
        __shared__ unsigned s_prefix;
        __shared__ int s_need;

#pragma unroll
        for (int l = 0; l < 4; l++) {
            const int shift = SH[l];
            const int nb = 1 << (curShift - shift);
            for (int i = t; i < nb; i += 256) hist[i] = 0;
            __syncthreads();
            for (int i = t; i < DHID; i += 256) {
                unsigned b = __float_as_uint(zr[i]);
                if (curShift >= 32 || (b >> curShift) == prefix)
                    atomicAdd(&hist[(b >> shift) & (nb - 1)], 1);
            }
            __syncthreads();
            if (t == 0) {
                int nd = need, bb;
                for (bb = nb - 1; bb > 0; bb--) {
                    int c = hist[bb];
                    if (c >= nd) break;
                    nd -= c;
                }
                s_prefix = (prefix << (curShift - shift)) | (unsigned)bb;
                s_need = nd;
            }
            __syncthreads();
            prefix = s_prefix;
            need = s_need;
            curShift = shift;
            __syncthreads();
        }

        const float Tf = __uint_as_float(prefix);
        const float hi = Tf + BANDM, lo = Tf - BANDM;
        for (int i = t; i < DHID; i += 256) {
            float v = zr[i];
            if (v > hi) {
                int s = atomicAdd(&sureCnt, 1);
                sv_s[s] = v;
                si_s[s] = i;
                z_sp[(size_t)row * DHID + i] = v;
            } else if (v >= lo) {
                int e = atomicAdd(&bandCnt, 1);
                if (e < BANDCAP) { bidx[e] = i; bval[e] = v; }
            }
        }
    }
    __syncthreads();

    // ---- inline fp64 band refinement ----
    const int sure = sureCnt;
    const int bc   = min(bandCnt, BANDCAP);
    const int need = TOPK - sure;

    if (bc > need) {   // contested: exact fp64 ranking
        // cache x row in smem once (each candidate re-reads it 32x otherwise)
        for (int j = t; j < DIN; j += 256) xs[j] = x[(size_t)row * DIN + j];
        __syncthreads();
        const int wd = t >> 5, lane = t & 31;
        for (int c = wd; c < bc; c += 8) {
            const float* wr = Wenc + (size_t)bidx[c] * DIN;
            double s = 0.0;
            for (int j = lane; j < DIN; j += 32)
                s += (double)xs[j] * (double)wr[j];
#pragma unroll
            for (int o = 16; o; o >>= 1)
                s += __shfl_down_sync(0xffffffffu, s, o);
            if (lane == 0) sc[c] = s;
        }
    }
    __syncthreads();

    if (t == 0) {
        int nsel = 0;
        int sel[BANDCAP];
        if (bc <= need) {
            for (int c = 0; c < bc; c++) sel[nsel++] = c;
        } else {
            bool taken[BANDCAP];
            for (int c = 0; c < bc; c++) taken[c] = false;
            for (int r = 0; r < need; r++) {
                int best = -1;
                for (int c = 0; c < bc; c++) {
                    if (taken[c]) continue;
                    if (best < 0 || sc[c] > sc[best] ||
                        (sc[c] == sc[best] && bidx[c] < bidx[best])) best = c;
                }
                taken[best] = true;
                sel[nsel++] = best;
            }
        }
        for (int a = 0; a < nsel; a++) {
            int c = sel[a];
            sv_s[sure + a] = bval[c];
            si_s[sure + a] = bidx[c];
            z_sp[(size_t)row * DHID + bidx[c]] = bval[c];
        }
        for (int a = sure + nsel; a < TOPK; a++) { sv_s[a] = 0.f; si_s[a] = 0; }
        // sort the 32 by index (smem, serial but tiny)
        for (int a = 1; a < TOPK; a++) {
            float v = sv_s[a]; int ix = si_s[a];
            int b = a - 1;
            while (b >= 0 && si_s[b] > ix) {
                sv_s[b + 1] = sv_s[b]; si_s[b + 1] = si_s[b]; b--;
            }
            sv_s[b + 1] = v; si_s[b + 1] = ix;
        }
        int pos = 0;
        for (int a = 0; a < TOPK; a++)
            if (sv_s[a] > 0.f) pos++;
        atomicAdd(&g_pos, pos);
    }
    __syncthreads();

    // ---- inline decoder: x_hat[row,:] = sum_k sv * WdecT[si,:] (fp16 w) ----
    const int d = t * 4;
    float x0 = 0.f, x1 = 0.f, x2 = 0.f, x3 = 0.f;
#pragma unroll
    for (int k = 0; k < TOPK; k++) {
        const float v = sv_s[k];
        const uint2 w8 = *(const uint2*)(WdecT + (size_t)si_s[k] * DIN + d);
        const __half2 w01 = *reinterpret_cast<const __half2*>(&w8.x);
        const __half2 w23 = *reinterpret_cast<const __half2*>(&w8.y);
        const float2 f01 = __half22float2(w01);
        const float2 f23 = __half22float2(w23);
        x0 += v * f01.x; x1 += v * f01.y; x2 += v * f23.x; x3 += v * f23.y;
    }
    *(float4*)(xhat + (size_t)row * DIN + d) = make_float4(x0, x1, x2, x3);

    // ---- last block writes `active` ----
    if (t == 0) {
        __threadfence();
        int done = atomicAdd(&g_done, 1);
        if (done == NROWS - 1) {
            int total = atomicAdd(&g_pos, 0);
            *act = (float)total / (float)NROWS;
        }
    }
}

// ---------------- launch ----------------
extern "C" void kernel_launch(void* const* d_in, const int* in_sizes, int n_in,
                              void* d_out, int out_size) {
    const float* x     = (const float*)d_in[0];
    const float* W_enc = (const float*)d_in[1];
    const float* W_dec = (const float*)d_in[2];
    float* out = (float*)d_out;

    float* xhat = out + OFF_XHAT;
    float* z_sp = out + OFF_ZSP;
    float* z    = out + OFF_Z;
    float* act  = out + OFF_ACT;

    __half* WdecT;
    cudaGetSymbolAddress((void**)&WdecT, g_WdecT);
    unsigned char *xh, *wh;
    cudaGetSymbolAddress((void**)&xh, g_xh);
    cudaGetSymbolAddress((void**)&wh, g_wh);

    cudaFuncSetAttribute(mma_gemm_kernel, cudaFuncAttributeMaxDynamicSharedMemorySize, GEMM_SMEM);

    prep_kernel<<<12320, 256>>>(x, W_enc, (uint4*)xh, (uint4*)wh);
    mma_gemm_kernel<<<dim3(DHID / 128, NROWS / 128), 256, GEMM_SMEM>>>(xh, wh, W_dec, WdecT, z, z_sp);
    select_kernel<<<NROWS, 256>>>(z, x, W_enc, WdecT, z_sp, xhat, act);
}

// round 14
// speedup vs baseline: 6.5126x; 1.0908x over previous
#include <cuda_runtime.h>
#include <cuda_bf16.h>
#include <cuda_fp16.h>
#include <cstdint>

// Problem constants
#define NROWS   8192
#define DIN     1024
#define DHID    16384
#define TOPK    32
#define BANDCAP 64
#define CAP     1024          // candidate buffer per row
#define TAU     0.78f         // static candidate threshold (~2.3 sigma)
#define BANDM   1e-3f         // refinement band half-width

// Output layout:
//   x_hat    [8192,1024]   @ 0
//   z_sparse [8192,16384]  @ 8388608
//   z        [8192,16384]  @ 142606336
//   active   scalar        @ 276824064
#define OFF_XHAT   0
#define OFF_ZSP    8388608
#define OFF_Z      142606336
#define OFF_ACT    276824064

// -------- device scratch (no allocations allowed) --------
__device__ __half g_WdecT[(size_t)DHID * DIN];                               // 32 MB fp16
__device__ __align__(256) unsigned char g_xh[(size_t)NROWS * DIN * 2];       // fp16 x
__device__ __align__(256) unsigned char g_wh[(size_t)DHID * DIN * 2];        // fp16 W_enc
__device__ uint2 g_cand[(size_t)NROWS * CAP];                                // 64 MB (valbits, idx)
__device__ int   g_cand_cnt[NROWS];
__device__ int   g_pos;
__device__ int   g_done;

// ---------------- PTX helpers (baseline compute_103 feature set only) -------
__device__ __forceinline__ uint32_t smem_u32(const void* p) {
    uint32_t a;
    asm("{ .reg .u64 t; cvta.to.shared.u64 t, %1; cvt.u32.u64 %0, t; }" : "=r"(a) : "l"(p));
    return a;
}
__device__ __forceinline__ void cp16(uint32_t dst, const void* src) {
    asm volatile("cp.async.cg.shared.global [%0], [%1], 16;" :: "r"(dst), "l"(src));
}
#define CP_COMMIT() asm volatile("cp.async.commit_group;" ::: "memory")
#define CP_WAIT1()  asm volatile("cp.async.wait_group 1;" ::: "memory")

__device__ __forceinline__ void ldm4(uint32_t* d, uint32_t addr) {
    asm volatile("ldmatrix.sync.aligned.m8n8.x4.shared.b16 {%0,%1,%2,%3}, [%4];"
        : "=r"(d[0]), "=r"(d[1]), "=r"(d[2]), "=r"(d[3]) : "r"(addr));
}
__device__ __forceinline__ void mma_f16(float* c, const uint32_t* a, const uint32_t* b) {
    asm volatile("mma.sync.aligned.m16n8k16.row.col.f32.f16.f16.f32 "
        "{%0,%1,%2,%3}, {%4,%5,%6,%7}, {%8,%9}, {%0,%1,%2,%3};"
        : "+f"(c[0]), "+f"(c[1]), "+f"(c[2]), "+f"(c[3])
        : "r"(a[0]), "r"(a[1]), "r"(a[2]), "r"(a[3]), "r"(b[0]), "r"(b[1]));
}

// conflict-free chunk swizzle for 128B rows (8 x 16B chunks):
// 8 consecutive rows at the same c16 hit 8 distinct 16B lanes.
__device__ __forceinline__ uint32_t swz(int r, int c16) {
    return (uint32_t)(r * 128 + ((c16 ^ (r & 7)) << 4));
}

// ---------------- prep: pack W_enc + pack x + reset --------------------------
// block ranges:
//   [0, 8192)        pack W_enc -> fp16      (2048 elems each)
//   [8192, 12288)    pack x -> fp16          (4096 blocks)
//   [12288, 12320)   reset counters          (32 blocks)
__global__ void prep_kernel(const float* __restrict__ x,
                            const float* __restrict__ Wenc,
                            uint4* __restrict__ xh, uint4* __restrict__ wh) {
    const int b = blockIdx.x, t = threadIdx.x;
    if (b < 12288) {
        const bool isW = (b < 8192);
        const int i = (isW ? b : (b - 8192)) * 256 + t;
        const float4* src = (const float4*)(isW ? Wenc : x);
        uint4* dst = isW ? wh : xh;
        float4 a = src[2 * i], c = src[2 * i + 1];
        __half2 h0 = __floats2half2_rn(a.x, a.y);
        __half2 h1 = __floats2half2_rn(a.z, a.w);
        __half2 h2 = __floats2half2_rn(c.x, c.y);
        __half2 h3 = __floats2half2_rn(c.z, c.w);
        uint4 o;
        o.x = *reinterpret_cast<unsigned*>(&h0);
        o.y = *reinterpret_cast<unsigned*>(&h1);
        o.z = *reinterpret_cast<unsigned*>(&h2);
        o.w = *reinterpret_cast<unsigned*>(&h3);
        dst[i] = o;
    } else {
        const int i = (b - 12288) * 256 + t;
        if (i < NROWS) g_cand_cnt[i] = 0;
        if (i == 0) { g_pos = 0; g_done = 0; }
    }
}

// ---------------- encoder: fp16 HMMA GEMM + relu + z_sp zeros + candidates --
// KTILE=64: half the barrier rounds of the KTILE=32 version.
// Prologue: each CTA transposes 2 W_dec 32x32 tiles into fp16 WdecT (scratch
// in not-yet-live stage smem); completion before select is implied by order.
#define KTILE   64
#define STAGES  3
#define TILE_B  16384
#define STAGE_B 32768
#define GEMM_SMEM (STAGES * STAGE_B)

__global__ __launch_bounds__(256, 2)
void mma_gemm_kernel(const unsigned char* __restrict__ Ah,
                     const unsigned char* __restrict__ Bh,
                     const float* __restrict__ Wdec,
                     __half* __restrict__ WdecT,
                     float* __restrict__ z, float* __restrict__ z_sp) {
    extern __shared__ unsigned char smem[];
    const uint32_t sb = smem_u32(smem);
    const int tid = threadIdx.x;
    const int lane = tid & 31, warp = tid >> 5;
    const int wm = warp & 3, wn = warp >> 2;
    const int m0 = blockIdx.y * 128, n0 = blockIdx.x * 128;

    // ---- prologue: transpose 2 W_dec tiles using stage smem as scratch ----
    {
        float (*tile)[33] = reinterpret_cast<float (*)[33]>(smem);
        const int L = blockIdx.y * gridDim.x + blockIdx.x;   // 0..8191
        const int tx = tid & 31, ty = tid >> 5;              // (32, 8)
#pragma unroll
        for (int q = 0; q < 2; q++) {
            const int tt = 2 * L + q;
            const int h0 = (tt & 511) * 32;
            const int d0 = (tt >> 9) * 32;
#pragma unroll
            for (int j = 0; j < 32; j += 8)
                tile[ty + j][tx] = Wdec[(size_t)(d0 + ty + j) * DHID + h0 + tx];
            __syncthreads();
#pragma unroll
            for (int j = 0; j < 32; j += 8)
                WdecT[(size_t)(h0 + ty + j) * DIN + d0 + tx] = __float2half(tile[tx][ty + j]);
            __syncthreads();
        }
    }

    float acc[2][8][4];
#pragma unroll
    for (int i = 0; i < 2; i++)
#pragma unroll
        for (int j = 0; j < 8; j++)
#pragma unroll
            for (int q = 0; q < 4; q++) acc[i][j][q] = 0.f;

    // stage loader: 2 subtiles x 1024 16B-chunks, 8 cp.async per thread
    auto load_stage = [&](int s, int kc) {
        const uint32_t stage = sb + s * STAGE_B;
#pragma unroll
        for (int t = 0; t < 2; t++) {
            const int r0 = t ? n0 : m0;
            const unsigned char* g = t ? Bh : Ah;
#pragma unroll
            for (int rep = 0; rep < 4; rep++) {
                const int j = tid + rep * 256;
                const int r = j >> 3, c16 = j & 7;
                const unsigned char* src = g + (((size_t)(r0 + r) << 10) + kc * 64 + c16 * 8) * 2;
                cp16(stage + t * TILE_B + swz(r, c16), src);
            }
        }
    };

    load_stage(0, 0); CP_COMMIT();
    load_stage(1, 1); CP_COMMIT();

    for (int kc = 0; kc < DIN / KTILE; kc++) {      // 16 iterations
        CP_WAIT1();                      // stage kc's data complete
        __syncthreads();                 // all threads done reading stage kc-1
        if (kc + 2 < DIN / KTILE) load_stage((kc + 2) % STAGES, kc + 2);
        CP_COMMIT();
        const uint32_t stage = sb + (kc % STAGES) * STAGE_B;

#pragma unroll
        for (int ks = 0; ks < 4; ks++) {
            uint32_t ah[2][4], bh[8][2];
#pragma unroll
            for (int i = 0; i < 2; i++) {
                const int row = wm * 32 + i * 16 + (lane & 15);
                const int c16 = ks * 2 + (lane >> 4);
                ldm4(ah[i], stage + swz(row, c16));
            }
#pragma unroll
            for (int g = 0; g < 4; g++) {
                const int row = wn * 64 + g * 16 + (lane & 7) + ((lane >> 4) << 3);
                const int c16 = ks * 2 + ((lane >> 3) & 1);
                uint32_t d[4];
                ldm4(d, stage + TILE_B + swz(row, c16));
                bh[2 * g][0] = d[0]; bh[2 * g][1] = d[1];
                bh[2 * g + 1][0] = d[2]; bh[2 * g + 1][1] = d[3];
            }
#pragma unroll
            for (int i = 0; i < 2; i++)
#pragma unroll
                for (int j = 0; j < 8; j++)
                    mma_f16(acc[i][j], ah[i], bh[j]);
        }
    }

    // epilogue: relu + z store + z_sp zero store + candidate push (v > TAU)
    const int mbase = m0 + wm * 32, nbase = n0 + wn * 64;
    const float2 zero2 = make_float2(0.f, 0.f);
#pragma unroll
    for (int i = 0; i < 2; i++)
#pragma unroll
        for (int j = 0; j < 8; j++) {
            const int r = mbase + i * 16 + (lane >> 2);
            const int c = nbase + j * 8 + (lane & 3) * 2;
            float2 v0, v1;
            v0.x = fmaxf(acc[i][j][0], 0.f); v0.y = fmaxf(acc[i][j][1], 0.f);
            v1.x = fmaxf(acc[i][j][2], 0.f); v1.y = fmaxf(acc[i][j][3], 0.f);
            *(float2*)(z + (size_t)r * DHID + c) = v0;
            *(float2*)(z + (size_t)(r + 8) * DHID + c) = v1;
            *(float2*)(z_sp + (size_t)r * DHID + c) = zero2;
            *(float2*)(z_sp + (size_t)(r + 8) * DHID + c) = zero2;
            if (v0.x > TAU) { int s = atomicAdd(&g_cand_cnt[r], 1);
                if (s < CAP) g_cand[(size_t)r * CAP + s] = make_uint2(__float_as_uint(v0.x), c); }
            if (v0.y > TAU) { int s = atomicAdd(&g_cand_cnt[r], 1);
                if (s < CAP) g_cand[(size_t)r * CAP + s] = make_uint2(__float_as_uint(v0.y), c + 1); }
            if (v1.x > TAU) { int s = atomicAdd(&g_cand_cnt[r + 8], 1);
                if (s < CAP) g_cand[(size_t)(r + 8) * CAP + s] = make_uint2(__float_as_uint(v1.x), c); }
            if (v1.y > TAU) { int s = atomicAdd(&g_cand_cnt[r + 8], 1);
                if (s < CAP) g_cand[(size_t)(r + 8) * CAP + s] = make_uint2(__float_as_uint(v1.y), c + 1); }
        }
}

// ---------------- merged: top-k + fallback + fp64 refine + decoder + active -
// One block (256 threads) per row; the last block to finish writes `active`.
__global__ void select_kernel(const float* __restrict__ z,
                              const float* __restrict__ x,
                              const float* __restrict__ Wenc,
                              const __half* __restrict__ WdecT,
                              float* __restrict__ z_sp,
                              float* __restrict__ xhat,
                              float* __restrict__ act) {
    __shared__ float cv[CAP];
    __shared__ int   ci[CAP];
    __shared__ int   hist[2048];
    __shared__ float xs[DIN];
    __shared__ float sT;
    __shared__ int sureCnt, bandCnt;
    __shared__ int   bidx[BANDCAP];
    __shared__ float bval[BANDCAP];
    __shared__ double sc[BANDCAP];
    __shared__ float sv_s[TOPK];
    __shared__ int   si_s[TOPK];

    const int row = blockIdx.x, t = threadIdx.x;
    const int cnt = g_cand_cnt[row];
    if (t == 0) { sureCnt = 0; bandCnt = 0; }
    __syncthreads();

    if (cnt >= 48 && cnt <= CAP) {
        // ---- fast path: rank-select over candidates ----
        for (int i = t; i < cnt; i += 256) {
            uint2 p = g_cand[(size_t)row * CAP + i];
            cv[i] = __uint_as_float(p.x);
            ci[i] = (int)p.y;
        }
        __syncthreads();

        // exact rank under strict total order (value desc, index asc)
        for (int c = t; c < cnt; c += 256) {
            float v = cv[c]; int ix = ci[c];
            int rank = 0;
            for (int j = 0; j < cnt; j++) {
                float u = cv[j];
                rank += (u > v) || (u == v && ci[j] < ix);
            }
            if (rank == TOPK - 1) sT = v;
        }
        __syncthreads();

        const float T = sT, hi = T + BANDM, lo = T - BANDM;
        for (int c = t; c < cnt; c += 256) {
            float v = cv[c];
            if (v > hi) {
                int s = atomicAdd(&sureCnt, 1);
                sv_s[s] = v;
                si_s[s] = ci[c];
                z_sp[(size_t)row * DHID + ci[c]] = v;
            } else if (v >= lo) {
                int e = atomicAdd(&bandCnt, 1);
                if (e < BANDCAP) { bidx[e] = ci[c]; bval[e] = v; }
            }
        }
    } else {
        // ---- fallback: dense radix-select over the z row ----
        const float* zr = z + (size_t)row * DHID;
        unsigned prefix = 0;
        int curShift = 32;
        int need = TOPK;
        const int SH[4] = {21, 13, 5, 0};
        __shared__ unsigned s_prefix;
        __shared__ int s_need;

#pragma unroll
        for (int l = 0; l < 4; l++) {
            const int shift = SH[l];
            const int nb = 1 << (curShift - shift);
            for (int i = t; i < nb; i += 256) hist[i] = 0;
            __syncthreads();
            for (int i = t; i < DHID; i += 256) {
                unsigned b = __float_as_uint(zr[i]);
                if (curShift >= 32 || (b >> curShift) == prefix)
                    atomicAdd(&hist[(b >> shift) & (nb - 1)], 1);
            }
            __syncthreads();
            if (t == 0) {
                int nd = need, bb;
                for (bb = nb - 1; bb > 0; bb--) {
                    int c = hist[bb];
                    if (c >= nd) break;
                    nd -= c;
                }
                s_prefix = (prefix << (curShift - shift)) | (unsigned)bb;
                s_need = nd;
            }
            __syncthreads();
            prefix = s_prefix;
            need = s_need;
            curShift = shift;
            __syncthreads();
        }

        const float Tf = __uint_as_float(prefix);
        const float hi = Tf + BANDM, lo = Tf - BANDM;
        for (int i = t; i < DHID; i += 256) {
            float v = zr[i];
            if (v > hi) {
                int s = atomicAdd(&sureCnt, 1);
                sv_s[s] = v;
                si_s[s] = i;
                z_sp[(size_t)row * DHID + i] = v;
            } else if (v >= lo) {
                int e = atomicAdd(&bandCnt, 1);
                if (e < BANDCAP) { bidx[e] = i; bval[e] = v; }
            }
        }
    }
    __syncthreads();

    // ---- inline fp64 band refinement ----
    const int sure = sureCnt;
    const int bc   = min(bandCnt, BANDCAP);
    const int need = TOPK - sure;

    if (bc > need) {   // contested: exact fp64 ranking
        // cache x row in smem once
        for (int j = t; j < DIN; j += 256) xs[j] = x[(size_t)row * DIN + j];
        __syncthreads();
        const int wd = t >> 5, lane = t & 31;
        for (int c = wd; c < bc; c += 8) {
            const float* wr = Wenc + (size_t)bidx[c] * DIN;
            double s = 0.0;
            for (int j = lane; j < DIN; j += 32)
                s += (double)xs[j] * (double)wr[j];
#pragma unroll
            for (int o = 16; o; o >>= 1)
                s += __shfl_down_sync(0xffffffffu, s, o);
            if (lane == 0) sc[c] = s;
        }
    }
    __syncthreads();

    if (t == 0) {
        int nsel = 0;
        int sel[BANDCAP];
        if (bc <= need) {
            for (int c = 0; c < bc; c++) sel[nsel++] = c;
        } else {
            bool taken[BANDCAP];
            for (int c = 0; c < bc; c++) taken[c] = false;
            for (int r = 0; r < need; r++) {
                int best = -1;
                for (int c = 0; c < bc; c++) {
                    if (taken[c]) continue;
                    if (best < 0 || sc[c] > sc[best] ||
                        (sc[c] == sc[best] && bidx[c] < bidx[best])) best = c;
                }
                taken[best] = true;
                sel[nsel++] = best;
            }
        }
        for (int a = 0; a < nsel; a++) {
            int c = sel[a];
            sv_s[sure + a] = bval[c];
            si_s[sure + a] = bidx[c];
            z_sp[(size_t)row * DHID + bidx[c]] = bval[c];
        }
        for (int a = sure + nsel; a < TOPK; a++) { sv_s[a] = 0.f; si_s[a] = 0; }
        // sort the 32 by index
        for (int a = 1; a < TOPK; a++) {
            float v = sv_s[a]; int ix = si_s[a];
            int b = a - 1;
            while (b >= 0 && si_s[b] > ix) {
                sv_s[b + 1] = sv_s[b]; si_s[b + 1] = si_s[b]; b--;
            }
            sv_s[b + 1] = v; si_s[b + 1] = ix;
        }
        int pos = 0;
        for (int a = 0; a < TOPK; a++)
            if (sv_s[a] > 0.f) pos++;
        atomicAdd(&g_pos, pos);
    }
    __syncthreads();

    // ---- inline decoder: x_hat[row,:] = sum_k sv * WdecT[si,:] (fp16 w) ----
    const int d = t * 4;
    float x0 = 0.f, x1 = 0.f, x2 = 0.f, x3 = 0.f;
#pragma unroll
    for (int k = 0; k < TOPK; k++) {
        const float v = sv_s[k];
        const uint2 w8 = *(const uint2*)(WdecT + (size_t)si_s[k] * DIN + d);
        const __half2 w01 = *reinterpret_cast<const __half2*>(&w8.x);
        const __half2 w23 = *reinterpret_cast<const __half2*>(&w8.y);
        const float2 f01 = __half22float2(w01);
        const float2 f23 = __half22float2(w23);
        x0 += v * f01.x; x1 += v * f01.y; x2 += v * f23.x; x3 += v * f23.y;
    }
    *(float4*)(xhat + (size_t)row * DIN + d) = make_float4(x0, x1, x2, x3);

    // ---- last block writes `active` ----
    if (t == 0) {
        __threadfence();
        int done = atomicAdd(&g_done, 1);
        if (done == NROWS - 1) {
            int total = atomicAdd(&g_pos, 0);
            *act = (float)total / (float)NROWS;
        }
    }
}

// ---------------- launch ----------------
extern "C" void kernel_launch(void* const* d_in, const int* in_sizes, int n_in,
                              void* d_out, int out_size) {
    const float* x     = (const float*)d_in[0];
    const float* W_enc = (const float*)d_in[1];
    const float* W_dec = (const float*)d_in[2];
    float* out = (float*)d_out;

    float* xhat = out + OFF_XHAT;
    float* z_sp = out + OFF_ZSP;
    float* z    = out + OFF_Z;
    float* act  = out + OFF_ACT;

    __half* WdecT;
    cudaGetSymbolAddress((void**)&WdecT, g_WdecT);
    unsigned char *xh, *wh;
    cudaGetSymbolAddress((void**)&xh, g_xh);
    cudaGetSymbolAddress((void**)&wh, g_wh);

    cudaFuncSetAttribute(mma_gemm_kernel, cudaFuncAttributeMaxDynamicSharedMemorySize, GEMM_SMEM);

    prep_kernel<<<12320, 256>>>(x, W_enc, (uint4*)xh, (uint4*)wh);
    mma_gemm_kernel<<<dim3(DHID / 128, NROWS / 128), 256, GEMM_SMEM>>>(xh, wh, W_dec, WdecT, z, z_sp);
    select_kernel<<<NROWS, 256>>>(z, x, W_enc, WdecT, z_sp, xhat, act);
}